// round 2
// baseline (speedup 1.0000x reference)
#include <cuda_runtime.h>

#define Bb  2
#define Ss  2048
#define Dd  1024
#define Hh  16
#define DKk 64
#define Mm  (Bb*Ss)

// Scratch (allocation-free: device globals)
__device__ float g_Q[(size_t)Bb*Hh*Ss*DKk];   // [B,H,S,DK]
__device__ float g_K[(size_t)Bb*Hh*Ss*DKk];
__device__ float g_V[(size_t)Bb*Hh*Ss*DKk];
__device__ float g_X[(size_t)Bb*Ss*Dd];       // attention out, [B,S,D]

// ---------------------------------------------------------------------------
// SGEMM: C[M,N] = A[M,K] * W[K,N] + bias   (M=4096, N=K=1024)
// permute=0: C row-major [M,N].  permute=1: C as [B,H,S,DK].
// ---------------------------------------------------------------------------
#define BM 128
#define BN 128
#define BK 16

__global__ __launch_bounds__(256) void sgemm_kernel(
    const float* __restrict__ A, const float* __restrict__ W,
    const float* __restrict__ bias, float* __restrict__ C, int permute)
{
    __shared__ float As[BK][132];   // [k][m], padded (132%32=4) for vec loads
    __shared__ float Bs[BK][BN];    // [k][n]

    const int tid = threadIdx.x;
    const int bm  = blockIdx.y * BM;
    const int bn  = blockIdx.x * BN;
    const int K = Dd, N = Dd;

    const int a_r = tid >> 2;           // 0..63
    const int a_c = (tid & 3) << 2;     // 0,4,8,12
    const int b_r = tid >> 5;           // 0..7
    const int b_c = (tid & 31) << 2;    // 0..124
    const int tr  = (tid >> 4) << 3;    // 0..120
    const int tc  = (tid & 15) << 3;    // 0..120

    float acc[8][8];
    #pragma unroll
    for (int i = 0; i < 8; i++)
        #pragma unroll
        for (int j = 0; j < 8; j++) acc[i][j] = 0.f;

    for (int k0 = 0; k0 < K; k0 += BK) {
        #pragma unroll
        for (int t = 0; t < 2; t++) {
            int r = a_r + t * 64;
            float4 va = *(const float4*)&A[(size_t)(bm + r) * K + k0 + a_c];
            As[a_c + 0][r] = va.x; As[a_c + 1][r] = va.y;
            As[a_c + 2][r] = va.z; As[a_c + 3][r] = va.w;
        }
        #pragma unroll
        for (int t = 0; t < 2; t++) {
            int r = b_r + t * 8;
            *(float4*)&Bs[r][b_c] =
                *(const float4*)&W[(size_t)(k0 + r) * N + bn + b_c];
        }
        __syncthreads();

        #pragma unroll
        for (int kk = 0; kk < BK; kk++) {
            float af[8], bf[8];
            *(float4*)&af[0] = *(const float4*)&As[kk][tr];
            *(float4*)&af[4] = *(const float4*)&As[kk][tr + 4];
            *(float4*)&bf[0] = *(const float4*)&Bs[kk][tc];
            *(float4*)&bf[4] = *(const float4*)&Bs[kk][tc + 4];
            #pragma unroll
            for (int i = 0; i < 8; i++)
                #pragma unroll
                for (int j = 0; j < 8; j++)
                    acc[i][j] += af[i] * bf[j];
        }
        __syncthreads();
    }

    float bb[8];
    #pragma unroll
    for (int j = 0; j < 8; j++) bb[j] = bias[bn + tc + j];

    if (permute == 0) {
        #pragma unroll
        for (int i = 0; i < 8; i++) {
            float4 v0, v1;
            v0.x = acc[i][0] + bb[0]; v0.y = acc[i][1] + bb[1];
            v0.z = acc[i][2] + bb[2]; v0.w = acc[i][3] + bb[3];
            v1.x = acc[i][4] + bb[4]; v1.y = acc[i][5] + bb[5];
            v1.z = acc[i][6] + bb[6]; v1.w = acc[i][7] + bb[7];
            size_t row = (size_t)(bm + tr + i);
            *(float4*)&C[row * N + bn + tc]     = v0;
            *(float4*)&C[row * N + bn + tc + 4] = v1;
        }
    } else {
        // n -> (h, dk); tc groups of 8 never cross a 64-wide head boundary
        int n0  = bn + tc;
        int h   = n0 >> 6;
        int dk0 = n0 & 63;
        #pragma unroll
        for (int i = 0; i < 8; i++) {
            int m = bm + tr + i;
            int b = m / Ss, s = m % Ss;
            float* dst = &C[(((size_t)(b * Hh + h)) * Ss + s) * DKk + dk0];
            float4 v0, v1;
            v0.x = acc[i][0] + bb[0]; v0.y = acc[i][1] + bb[1];
            v0.z = acc[i][2] + bb[2]; v0.w = acc[i][3] + bb[3];
            v1.x = acc[i][4] + bb[4]; v1.y = acc[i][5] + bb[5];
            v1.z = acc[i][6] + bb[6]; v1.w = acc[i][7] + bb[7];
            *(float4*)&dst[0] = v0;
            *(float4*)&dst[4] = v1;
        }
    }
}

// ---------------------------------------------------------------------------
// Flash attention, fp32, causal. Per block: one (b,h), 64 query rows.
// 128 threads: 4 "quad" lanes per row pair; each thread owns rows r0 and
// r0+32 and 16 of the 64 output dims (dk = i*4 + qd).
// KV tiles of 32 keys. Online softmax.
// ---------------------------------------------------------------------------
__global__ __launch_bounds__(128) void attn_kernel(
    const float* __restrict__ Qg, const float* __restrict__ Kg,
    const float* __restrict__ Vg, float* __restrict__ Xg)
{
    __shared__ float Qst[64][64];   // [d][r]  (transposed, conflict-free reads)
    __shared__ float Ks[32][65];    // [c][d]  pad 65: qd*65 % 32 distinct
    __shared__ float Vs[32][65];
    __shared__ float Pst[32][64];   // [c][r]  (broadcast reads)

    const int tid = threadIdx.x;
    const int bh  = blockIdx.y;        // 0..31  (b*H + h)
    const int iq  = blockIdx.x;        // 0..31  query tile
    const int qd  = tid & 3;
    const int r0  = tid >> 2;          // 0..31; rows r0 and r0+32

    const size_t base = (size_t)bh * Ss * DKk;
    const float* Qb = Qg + base + (size_t)iq * 64 * DKk;
    const float* Kb = Kg + base;
    const float* Vb = Vg + base;

    // load 64x64 Q tile transposed
    #pragma unroll
    for (int t = 0; t < 8; t++) {
        int idx = tid + t * 128;           // 0..1023
        int rr = idx >> 4;
        int cc = (idx & 15) << 2;
        float4 v = *(const float4*)&Qb[rr * DKk + cc];
        Qst[cc + 0][rr] = v.x; Qst[cc + 1][rr] = v.y;
        Qst[cc + 2][rr] = v.z; Qst[cc + 3][rr] = v.w;
    }

    float m0 = -1e30f, m1 = -1e30f, l0 = 0.f, l1 = 0.f;
    float o0[16], o1[16];
    #pragma unroll
    for (int i = 0; i < 16; i++) { o0[i] = 0.f; o1[i] = 0.f; }

    const int row0 = iq * 64 + r0;
    const int row1 = row0 + 32;
    const int jmax = 2 * iq + 1;

    for (int j = 0; j <= jmax; j++) {
        __syncthreads();
        #pragma unroll
        for (int t = 0; t < 4; t++) {
            int idx = tid + t * 128;       // 0..511
            int rr = idx >> 4;             // 0..31
            int cc = (idx & 15) << 2;
            float4 kv = *(const float4*)&Kb[(size_t)(j * 32 + rr) * DKk + cc];
            Ks[rr][cc + 0] = kv.x; Ks[rr][cc + 1] = kv.y;
            Ks[rr][cc + 2] = kv.z; Ks[rr][cc + 3] = kv.w;
            float4 vv = *(const float4*)&Vb[(size_t)(j * 32 + rr) * DKk + cc];
            Vs[rr][cc + 0] = vv.x; Vs[rr][cc + 1] = vv.y;
            Vs[rr][cc + 2] = vv.z; Vs[rr][cc + 3] = vv.w;
        }
        __syncthreads();

        // scores: s[i] for key c = j*32 + i*4 + qd, for both rows
        float s0[8], s1[8];
        #pragma unroll
        for (int i = 0; i < 8; i++) { s0[i] = 0.f; s1[i] = 0.f; }
        #pragma unroll 4
        for (int d = 0; d < 64; d++) {
            float q0 = Qst[d][r0];
            float q1 = Qst[d][r0 + 32];
            #pragma unroll
            for (int i = 0; i < 8; i++) {
                float kv = Ks[i * 4 + qd][d];
                s0[i] += q0 * kv;
                s1[i] += q1 * kv;
            }
        }
        const bool needmask = (j >= 2 * iq);
        #pragma unroll
        for (int i = 0; i < 8; i++) {
            int col = j * 32 + i * 4 + qd;
            s0[i] *= 0.125f;
            s1[i] *= 0.125f;
            if (needmask) {
                if (col > row0) s0[i] = -1e30f;
                if (col > row1) s1[i] = -1e30f;
            }
        }

        // ---- online softmax, row 0 ----
        {
            float mt = s0[0];
            #pragma unroll
            for (int i = 1; i < 8; i++) mt = fmaxf(mt, s0[i]);
            mt = fmaxf(mt, __shfl_xor_sync(0xffffffffu, mt, 1));
            mt = fmaxf(mt, __shfl_xor_sync(0xffffffffu, mt, 2));
            float mn = fmaxf(m0, mt);
            float alpha = __expf(m0 - mn);
            float ls = 0.f;
            #pragma unroll
            for (int i = 0; i < 8; i++) {
                float p = __expf(s0[i] - mn);
                Pst[i * 4 + qd][r0] = p;
                ls += p;
            }
            ls += __shfl_xor_sync(0xffffffffu, ls, 1);
            ls += __shfl_xor_sync(0xffffffffu, ls, 2);
            l0 = l0 * alpha + ls;
            m0 = mn;
            #pragma unroll
            for (int i = 0; i < 16; i++) o0[i] *= alpha;
        }
        // ---- online softmax, row 1 ----
        {
            float mt = s1[0];
            #pragma unroll
            for (int i = 1; i < 8; i++) mt = fmaxf(mt, s1[i]);
            mt = fmaxf(mt, __shfl_xor_sync(0xffffffffu, mt, 1));
            mt = fmaxf(mt, __shfl_xor_sync(0xffffffffu, mt, 2));
            float mn = fmaxf(m1, mt);
            float alpha = __expf(m1 - mn);
            float ls = 0.f;
            #pragma unroll
            for (int i = 0; i < 8; i++) {
                float p = __expf(s1[i] - mn);
                Pst[i * 4 + qd][r0 + 32] = p;
                ls += p;
            }
            ls += __shfl_xor_sync(0xffffffffu, ls, 1);
            ls += __shfl_xor_sync(0xffffffffu, ls, 2);
            l1 = l1 * alpha + ls;
            m1 = mn;
            #pragma unroll
            for (int i = 0; i < 16; i++) o1[i] *= alpha;
        }
        __syncwarp();

        // ---- PV: o[dk] += sum_c P[r][c] * V[c][dk], dk = i*4+qd ----
        #pragma unroll 8
        for (int c = 0; c < 32; c++) {
            float p0 = Pst[c][r0];
            float p1 = Pst[c][r0 + 32];
            #pragma unroll
            for (int i = 0; i < 16; i++) {
                float vv = Vs[c][i * 4 + qd];
                o0[i] += p0 * vv;
                o1[i] += p1 * vv;
            }
        }
        __syncwarp();
    }

    // epilogue: X[(b*S+s)*D + h*DK + dk]
    const float inv0 = 1.f / l0;
    const float inv1 = 1.f / l1;
    const int b = bh >> 4, h = bh & 15;
    float* out0 = Xg + ((size_t)(b * Ss + row0)) * Dd + h * DKk;
    float* out1 = Xg + ((size_t)(b * Ss + row1)) * Dd + h * DKk;
    #pragma unroll
    for (int i = 0; i < 16; i++) {
        out0[i * 4 + qd] = o0[i] * inv0;
        out1[i * 4 + qd] = o1[i] * inv1;
    }
}

// ---------------------------------------------------------------------------
extern "C" void kernel_launch(void* const* d_in, const int* in_sizes, int n_in,
                              void* d_out, int out_size)
{
    const float* q   = (const float*)d_in[0];
    const float* k   = (const float*)d_in[1];
    const float* v   = (const float*)d_in[2];
    // d_in[3] = causal mask (int32) — causality computed analytically
    const float* w_q = (const float*)d_in[4];
    const float* b_q = (const float*)d_in[5];
    const float* w_k = (const float*)d_in[6];
    const float* b_k = (const float*)d_in[7];
    const float* w_v = (const float*)d_in[8];
    const float* b_v = (const float*)d_in[9];
    const float* w_o = (const float*)d_in[10];
    const float* b_o = (const float*)d_in[11];
    float* out = (float*)d_out;

    float *pQ, *pK, *pV, *pX;
    cudaGetSymbolAddress((void**)&pQ, g_Q);
    cudaGetSymbolAddress((void**)&pK, g_K);
    cudaGetSymbolAddress((void**)&pV, g_V);
    cudaGetSymbolAddress((void**)&pX, g_X);

    dim3 ggrid(Dd / BN, Mm / BM);   // (8, 32)
    sgemm_kernel<<<ggrid, 256>>>(q, w_q, b_q, pQ, 1);
    sgemm_kernel<<<ggrid, 256>>>(k, w_k, b_k, pK, 1);
    sgemm_kernel<<<ggrid, 256>>>(v, w_v, b_v, pV, 1);

    dim3 agrid(Ss / 64, Bb * Hh);   // (32, 32)
    attn_kernel<<<agrid, 128>>>(pQ, pK, pV, pX);

    sgemm_kernel<<<ggrid, 256>>>(pX, w_o, b_o, out, 0);
}

// round 5
// speedup vs baseline: 1.3127x; 1.3127x over previous
#include <cuda_runtime.h>
#include <cuda_bf16.h>
#include <cstdint>

#define Bb  2
#define Ss  2048
#define Dd  1024
#define Hh  16
#define DKk 64
#define Mm  (Bb*Ss)

// ---------------- scratch (allocation-free: device globals) ----------------
__device__ float g_Q[(size_t)Bb*Hh*Ss*DKk];   // [B,H,S,DK]
__device__ float g_K[(size_t)Bb*Hh*Ss*DKk];
__device__ float g_V[(size_t)Bb*Hh*Ss*DKk];
__device__ float g_X[(size_t)Bb*Ss*Dd];       // attention out, [B,S,D]
__device__ __nv_bfloat16 g_Ahi[(size_t)Mm*Dd];   // activation hi/lo, K-major
__device__ __nv_bfloat16 g_Alo[(size_t)Mm*Dd];
__device__ __nv_bfloat16 g_Whi[(size_t)Dd*Dd];   // weight^T hi/lo, [N,K] K-major
__device__ __nv_bfloat16 g_Wlo[(size_t)Dd*Dd];

// ---------------- warp-MMA helpers (arch-portable PTX, no tcgen05) --------
__device__ __forceinline__ uint32_t smem_u32(const void* p) {
    uint32_t a;
    asm("{ .reg .u64 t; cvta.to.shared.u64 t, %1; cvt.u32.u64 %0, t; }"
        : "=r"(a) : "l"(p));
    return a;
}
__device__ __forceinline__ void ldsm4(uint32_t a, uint32_t& r0, uint32_t& r1,
                                      uint32_t& r2, uint32_t& r3) {
    asm volatile("ldmatrix.sync.aligned.m8n8.x4.shared.b16 {%0,%1,%2,%3}, [%4];"
                 : "=r"(r0), "=r"(r1), "=r"(r2), "=r"(r3) : "r"(a));
}
__device__ __forceinline__ void ldsm2(uint32_t a, uint32_t& r0, uint32_t& r1) {
    asm volatile("ldmatrix.sync.aligned.m8n8.x2.shared.b16 {%0,%1}, [%2];"
                 : "=r"(r0), "=r"(r1) : "r"(a));
}
__device__ __forceinline__ void mma16816(float* c, uint32_t a0, uint32_t a1,
                                         uint32_t a2, uint32_t a3,
                                         uint32_t b0, uint32_t b1) {
    asm volatile(
        "mma.sync.aligned.m16n8k16.row.col.f32.bf16.bf16.f32 "
        "{%0,%1,%2,%3}, {%4,%5,%6,%7}, {%8,%9}, {%0,%1,%2,%3};"
        : "+f"(c[0]), "+f"(c[1]), "+f"(c[2]), "+f"(c[3])
        : "r"(a0), "r"(a1), "r"(a2), "r"(a3), "r"(b0), "r"(b1));
}

// ---------------------------------------------------------------------------
// fp32 -> bf16 hi/lo split (activations, already K-major)
// ---------------------------------------------------------------------------
__global__ __launch_bounds__(256) void conv_act_kernel(
    const float* __restrict__ in, __nv_bfloat16* __restrict__ hi,
    __nv_bfloat16* __restrict__ lo)
{
    int i = blockIdx.x * blockDim.x + threadIdx.x;   // one float4
    float4 v = ((const float4*)in)[i];
    __nv_bfloat16 h0 = __float2bfloat16(v.x);
    __nv_bfloat16 h1 = __float2bfloat16(v.y);
    __nv_bfloat16 h2 = __float2bfloat16(v.z);
    __nv_bfloat16 h3 = __float2bfloat16(v.w);
    __nv_bfloat162* hp = (__nv_bfloat162*)hi;
    __nv_bfloat162* lp = (__nv_bfloat162*)lo;
    hp[i * 2 + 0] = __nv_bfloat162(h0, h1);
    hp[i * 2 + 1] = __nv_bfloat162(h2, h3);
    lp[i * 2 + 0] = __nv_bfloat162(
        __float2bfloat16(v.x - __bfloat162float(h0)),
        __float2bfloat16(v.y - __bfloat162float(h1)));
    lp[i * 2 + 1] = __nv_bfloat162(
        __float2bfloat16(v.z - __bfloat162float(h2)),
        __float2bfloat16(v.w - __bfloat162float(h3)));
}

// ---------------------------------------------------------------------------
// weight transpose + split: W[K,N] fp32 -> WT[N,K] bf16 hi/lo
// ---------------------------------------------------------------------------
__global__ __launch_bounds__(256) void conv_wt_kernel(
    const float* __restrict__ W, __nv_bfloat16* __restrict__ hiT,
    __nv_bfloat16* __restrict__ loT)
{
    __shared__ float ts[32][33];
    int tx = threadIdx.x, ty = threadIdx.y;          // 32 x 8
    int bn = blockIdx.x * 32, bk = blockIdx.y * 32;
    #pragma unroll
    for (int r = 0; r < 4; r++)
        ts[ty + r * 8][tx] = W[(size_t)(bk + ty + r * 8) * Dd + bn + tx];
    __syncthreads();
    #pragma unroll
    for (int r = 0; r < 4; r++) {
        float x = ts[tx][ty + r * 8];                // = W[bk+tx][bn+ty+r*8]
        __nv_bfloat16 h = __float2bfloat16(x);
        size_t o = (size_t)(bn + ty + r * 8) * Dd + bk + tx;
        hiT[o] = h;
        loT[o] = __float2bfloat16(x - __bfloat162float(h));
    }
}

// ---------------------------------------------------------------------------
// HMMA bf16x3 GEMM: C[4096,1024] = A * W + bias
// A as hi/lo bf16 [M,K]; W as hi/lo bf16 [N,K].
// CTA 128x128, K-chunk 32, 8 warps (2m x 4n), warp tile 64x32.
// 3 passes per chunk: Ah*Bh + Ah*Bl + Al*Bh.
// ---------------------------------------------------------------------------
#define KCH   32
#define NCHUNK (Dd / KCH)          // 32
#define SROW  40                   // padded halves per row (80B, LDSM conflict-free)
#define ABYTES (128 * SROW * 2)    // 10240 B per array

__global__ __launch_bounds__(256, 1) void hgemm_kernel(
    const __nv_bfloat16* __restrict__ Ahi, const __nv_bfloat16* __restrict__ Alo,
    const __nv_bfloat16* __restrict__ Whi, const __nv_bfloat16* __restrict__ Wlo,
    const float* __restrict__ bias, float* __restrict__ C, int permute)
{
    __shared__ __nv_bfloat16 sm[4 * 128 * SROW];   // [Ah|Al|Bh|Bl], 40KB

    const int tid  = threadIdx.x;
    const int wid  = tid >> 5, lane = tid & 31;
    const int bm   = blockIdx.y * 128, bn = blockIdx.x * 128;
    const int wm   = wid & 1;          // m half (64 rows)
    const int wn   = wid >> 1;         // n quarter (32 cols)

    float c[4][4][4];
    #pragma unroll
    for (int i = 0; i < 4; i++)
        #pragma unroll
        for (int j = 0; j < 4; j++)
            #pragma unroll
            for (int r = 0; r < 4; r++) c[i][j][r] = 0.f;

    // loader: 4 arrays x 512 uint4-units each; 2 units per thread per array
    const int u0 = tid, u1 = tid + 256;
    const int r0 = u0 >> 2, q0 = (u0 & 3) * 8;
    const int r1 = u1 >> 2, q1 = (u1 & 3) * 8;

    uint4 ld[8];
    #define LOAD_CHUNK(cc) do {                                                 \
        const int k0_ = (cc) * KCH;                                             \
        ld[0] = *(const uint4*)&Ahi[(size_t)(bm + r0) * Dd + k0_ + q0];         \
        ld[1] = *(const uint4*)&Ahi[(size_t)(bm + r1) * Dd + k0_ + q1];         \
        ld[2] = *(const uint4*)&Alo[(size_t)(bm + r0) * Dd + k0_ + q0];         \
        ld[3] = *(const uint4*)&Alo[(size_t)(bm + r1) * Dd + k0_ + q1];         \
        ld[4] = *(const uint4*)&Whi[(size_t)(bn + r0) * Dd + k0_ + q0];         \
        ld[5] = *(const uint4*)&Whi[(size_t)(bn + r1) * Dd + k0_ + q1];         \
        ld[6] = *(const uint4*)&Wlo[(size_t)(bn + r0) * Dd + k0_ + q0];         \
        ld[7] = *(const uint4*)&Wlo[(size_t)(bn + r1) * Dd + k0_ + q1];         \
    } while (0)
    #define STORE_CHUNK() do {                                                  \
        *(uint4*)&sm[0 * 128 * SROW + r0 * SROW + q0] = ld[0];                  \
        *(uint4*)&sm[0 * 128 * SROW + r1 * SROW + q1] = ld[1];                  \
        *(uint4*)&sm[1 * 128 * SROW + r0 * SROW + q0] = ld[2];                  \
        *(uint4*)&sm[1 * 128 * SROW + r1 * SROW + q1] = ld[3];                  \
        *(uint4*)&sm[2 * 128 * SROW + r0 * SROW + q0] = ld[4];                  \
        *(uint4*)&sm[2 * 128 * SROW + r1 * SROW + q1] = ld[5];                  \
        *(uint4*)&sm[3 * 128 * SROW + r0 * SROW + q0] = ld[6];                  \
        *(uint4*)&sm[3 * 128 * SROW + r1 * SROW + q1] = ld[7];                  \
    } while (0)

    const uint32_t sb = smem_u32(sm);
    const uint32_t aoff =
        sb + (uint32_t)(((wm * 64 + (lane & 15)) * SROW + (lane >> 4) * 8) * 2);
    const uint32_t boff =
        sb + (uint32_t)(((wn * 32 + (lane & 7)) * SROW + ((lane >> 3) & 1) * 8) * 2);

    LOAD_CHUNK(0);
    STORE_CHUNK();

    for (int cc = 0; cc < NCHUNK; cc++) {
        __syncthreads();                       // smem for chunk cc ready
        if (cc + 1 < NCHUNK) LOAD_CHUNK(cc + 1);

        #pragma unroll
        for (int pass = 0; pass < 3; pass++) {
            const uint32_t Ab = aoff + (pass == 2 ? ABYTES : 0);               // Al on pass 2
            const uint32_t Bbp = boff + 2 * ABYTES + (pass == 1 ? ABYTES : 0); // Bl on pass 1
            #pragma unroll
            for (int ks = 0; ks < 2; ks++) {
                uint32_t a[4][4], b[4][2];
                #pragma unroll
                for (int mi = 0; mi < 4; mi++)
                    ldsm4(Ab + mi * (16 * SROW * 2) + ks * 32,
                          a[mi][0], a[mi][1], a[mi][2], a[mi][3]);
                #pragma unroll
                for (int ni = 0; ni < 4; ni++)
                    ldsm2(Bbp + ni * (8 * SROW * 2) + ks * 32, b[ni][0], b[ni][1]);
                #pragma unroll
                for (int mi = 0; mi < 4; mi++)
                    #pragma unroll
                    for (int ni = 0; ni < 4; ni++)
                        mma16816(c[mi][ni], a[mi][0], a[mi][1], a[mi][2], a[mi][3],
                                 b[ni][0], b[ni][1]);
            }
        }
        __syncthreads();                       // compute done before overwrite
        if (cc + 1 < NCHUNK) STORE_CHUNK();
    }

    // ---- epilogue: bias + store (row-major or [B,H,S,DK]) ----
    const int mrow0 = bm + wm * 64 + (lane >> 2);
    const int ncol0 = bn + wn * 32 + (lane & 3) * 2;
    #pragma unroll
    for (int mi = 0; mi < 4; mi++) {
        #pragma unroll
        for (int h2 = 0; h2 < 2; h2++) {
            const int m = mrow0 + mi * 16 + h2 * 8;
            const int b = m >> 11, s = m & 2047;
            #pragma unroll
            for (int ni = 0; ni < 4; ni++) {
                const int n = ncol0 + ni * 8;
                float2 v;
                v.x = c[mi][ni][h2 * 2 + 0] + bias[n];
                v.y = c[mi][ni][h2 * 2 + 1] + bias[n + 1];
                if (permute == 0) {
                    *(float2*)&C[(size_t)m * Dd + n] = v;
                } else {
                    const int h = n >> 6, dk = n & 63;
                    *(float2*)&C[(((size_t)(b * Hh + h)) * Ss + s) * DKk + dk] = v;
                }
            }
        }
    }
}

// ---------------------------------------------------------------------------
// Flash attention, fp32, causal (unchanged)
// ---------------------------------------------------------------------------
__global__ __launch_bounds__(128) void attn_kernel(
    const float* __restrict__ Qg, const float* __restrict__ Kg,
    const float* __restrict__ Vg, float* __restrict__ Xg)
{
    __shared__ float Qst[64][64];
    __shared__ float Ks[32][65];
    __shared__ float Vs[32][65];
    __shared__ float Pst[32][64];

    const int tid = threadIdx.x;
    const int bh  = blockIdx.y;
    const int iq  = blockIdx.x;
    const int qd  = tid & 3;
    const int r0  = tid >> 2;

    const size_t base = (size_t)bh * Ss * DKk;
    const float* Qb = Qg + base + (size_t)iq * 64 * DKk;
    const float* Kb = Kg + base;
    const float* Vb = Vg + base;

    #pragma unroll
    for (int t = 0; t < 8; t++) {
        int idx = tid + t * 128;
        int rr = idx >> 4;
        int cc = (idx & 15) << 2;
        float4 v = *(const float4*)&Qb[rr * DKk + cc];
        Qst[cc + 0][rr] = v.x; Qst[cc + 1][rr] = v.y;
        Qst[cc + 2][rr] = v.z; Qst[cc + 3][rr] = v.w;
    }

    float m0 = -1e30f, m1 = -1e30f, l0 = 0.f, l1 = 0.f;
    float o0[16], o1[16];
    #pragma unroll
    for (int i = 0; i < 16; i++) { o0[i] = 0.f; o1[i] = 0.f; }

    const int row0 = iq * 64 + r0;
    const int row1 = row0 + 32;
    const int jmax = 2 * iq + 1;

    for (int j = 0; j <= jmax; j++) {
        __syncthreads();
        #pragma unroll
        for (int t = 0; t < 4; t++) {
            int idx = tid + t * 128;
            int rr = idx >> 4;
            int cc = (idx & 15) << 2;
            float4 kv = *(const float4*)&Kb[(size_t)(j * 32 + rr) * DKk + cc];
            Ks[rr][cc + 0] = kv.x; Ks[rr][cc + 1] = kv.y;
            Ks[rr][cc + 2] = kv.z; Ks[rr][cc + 3] = kv.w;
            float4 vv = *(const float4*)&Vb[(size_t)(j * 32 + rr) * DKk + cc];
            Vs[rr][cc + 0] = vv.x; Vs[rr][cc + 1] = vv.y;
            Vs[rr][cc + 2] = vv.z; Vs[rr][cc + 3] = vv.w;
        }
        __syncthreads();

        float s0[8], s1[8];
        #pragma unroll
        for (int i = 0; i < 8; i++) { s0[i] = 0.f; s1[i] = 0.f; }
        #pragma unroll 4
        for (int d = 0; d < 64; d++) {
            float q0 = Qst[d][r0];
            float q1 = Qst[d][r0 + 32];
            #pragma unroll
            for (int i = 0; i < 8; i++) {
                float kv = Ks[i * 4 + qd][d];
                s0[i] += q0 * kv;
                s1[i] += q1 * kv;
            }
        }
        const bool needmask = (j >= 2 * iq);
        #pragma unroll
        for (int i = 0; i < 8; i++) {
            int col = j * 32 + i * 4 + qd;
            s0[i] *= 0.125f;
            s1[i] *= 0.125f;
            if (needmask) {
                if (col > row0) s0[i] = -1e30f;
                if (col > row1) s1[i] = -1e30f;
            }
        }

        {
            float mt = s0[0];
            #pragma unroll
            for (int i = 1; i < 8; i++) mt = fmaxf(mt, s0[i]);
            mt = fmaxf(mt, __shfl_xor_sync(0xffffffffu, mt, 1));
            mt = fmaxf(mt, __shfl_xor_sync(0xffffffffu, mt, 2));
            float mn = fmaxf(m0, mt);
            float alpha = __expf(m0 - mn);
            float ls = 0.f;
            #pragma unroll
            for (int i = 0; i < 8; i++) {
                float p = __expf(s0[i] - mn);
                Pst[i * 4 + qd][r0] = p;
                ls += p;
            }
            ls += __shfl_xor_sync(0xffffffffu, ls, 1);
            ls += __shfl_xor_sync(0xffffffffu, ls, 2);
            l0 = l0 * alpha + ls;
            m0 = mn;
            #pragma unroll
            for (int i = 0; i < 16; i++) o0[i] *= alpha;
        }
        {
            float mt = s1[0];
            #pragma unroll
            for (int i = 1; i < 8; i++) mt = fmaxf(mt, s1[i]);
            mt = fmaxf(mt, __shfl_xor_sync(0xffffffffu, mt, 1));
            mt = fmaxf(mt, __shfl_xor_sync(0xffffffffu, mt, 2));
            float mn = fmaxf(m1, mt);
            float alpha = __expf(m1 - mn);
            float ls = 0.f;
            #pragma unroll
            for (int i = 0; i < 8; i++) {
                float p = __expf(s1[i] - mn);
                Pst[i * 4 + qd][r0 + 32] = p;
                ls += p;
            }
            ls += __shfl_xor_sync(0xffffffffu, ls, 1);
            ls += __shfl_xor_sync(0xffffffffu, ls, 2);
            l1 = l1 * alpha + ls;
            m1 = mn;
            #pragma unroll
            for (int i = 0; i < 16; i++) o1[i] *= alpha;
        }
        __syncwarp();

        #pragma unroll 8
        for (int ci = 0; ci < 32; ci++) {
            float p0 = Pst[ci][r0];
            float p1 = Pst[ci][r0 + 32];
            #pragma unroll
            for (int i = 0; i < 16; i++) {
                float vv = Vs[ci][i * 4 + qd];
                o0[i] += p0 * vv;
                o1[i] += p1 * vv;
            }
        }
        __syncwarp();
    }

    const float inv0 = 1.f / l0;
    const float inv1 = 1.f / l1;
    const int b = bh >> 4, h = bh & 15;
    float* out0 = Xg + ((size_t)(b * Ss + row0)) * Dd + h * DKk;
    float* out1 = Xg + ((size_t)(b * Ss + row1)) * Dd + h * DKk;
    #pragma unroll
    for (int i = 0; i < 16; i++) {
        out0[i * 4 + qd] = o0[i] * inv0;
        out1[i * 4 + qd] = o1[i] * inv1;
    }
}

// ---------------------------------------------------------------------------
extern "C" void kernel_launch(void* const* d_in, const int* in_sizes, int n_in,
                              void* d_out, int out_size)
{
    const float* q   = (const float*)d_in[0];
    const float* k   = (const float*)d_in[1];
    const float* v   = (const float*)d_in[2];
    // d_in[3] = causal mask (int32) — causality computed analytically
    const float* w_q = (const float*)d_in[4];
    const float* b_q = (const float*)d_in[5];
    const float* w_k = (const float*)d_in[6];
    const float* b_k = (const float*)d_in[7];
    const float* w_v = (const float*)d_in[8];
    const float* b_v = (const float*)d_in[9];
    const float* w_o = (const float*)d_in[10];
    const float* b_o = (const float*)d_in[11];
    float* out = (float*)d_out;

    float *pQ, *pK, *pV, *pX;
    __nv_bfloat16 *pAhi, *pAlo, *pWhi, *pWlo;
    cudaGetSymbolAddress((void**)&pQ,   g_Q);
    cudaGetSymbolAddress((void**)&pK,   g_K);
    cudaGetSymbolAddress((void**)&pV,   g_V);
    cudaGetSymbolAddress((void**)&pX,   g_X);
    cudaGetSymbolAddress((void**)&pAhi, g_Ahi);
    cudaGetSymbolAddress((void**)&pAlo, g_Alo);
    cudaGetSymbolAddress((void**)&pWhi, g_Whi);
    cudaGetSymbolAddress((void**)&pWlo, g_Wlo);

    const int conv_act_blocks = (Mm * Dd / 4) / 256;   // 4096
    dim3 wt_grid(32, 32), wt_block(32, 8);
    dim3 gemm_grid(Dd / 128, Mm / 128);                // (8, 32)

    conv_act_kernel<<<conv_act_blocks, 256>>>(q, pAhi, pAlo);
    conv_wt_kernel<<<wt_grid, wt_block>>>(w_q, pWhi, pWlo);
    hgemm_kernel<<<gemm_grid, 256>>>(pAhi, pAlo, pWhi, pWlo, b_q, pQ, 1);

    conv_act_kernel<<<conv_act_blocks, 256>>>(k, pAhi, pAlo);
    conv_wt_kernel<<<wt_grid, wt_block>>>(w_k, pWhi, pWlo);
    hgemm_kernel<<<gemm_grid, 256>>>(pAhi, pAlo, pWhi, pWlo, b_k, pK, 1);

    conv_act_kernel<<<conv_act_blocks, 256>>>(v, pAhi, pAlo);
    conv_wt_kernel<<<wt_grid, wt_block>>>(w_v, pWhi, pWlo);
    hgemm_kernel<<<gemm_grid, 256>>>(pAhi, pAlo, pWhi, pWlo, b_v, pV, 1);

    dim3 agrid(Ss / 64, Bb * Hh);                      // (32, 32)
    attn_kernel<<<agrid, 128>>>(pQ, pK, pV, pX);

    conv_act_kernel<<<conv_act_blocks, 256>>>(pX, pAhi, pAlo);
    conv_wt_kernel<<<wt_grid, wt_block>>>(w_o, pWhi, pWlo);
    hgemm_kernel<<<gemm_grid, 256>>>(pAhi, pAlo, pWhi, pWlo, b_o, out, 0);
}

// round 6
// speedup vs baseline: 2.7022x; 2.0585x over previous
#include <cuda_runtime.h>
#include <cuda_bf16.h>
#include <cstdint>

#define Bb  2
#define Ss  2048
#define Dd  1024
#define Hh  16
#define DKk 64
#define Mm  (Bb*Ss)

// ---------------- scratch (allocation-free: device globals) ----------------
__device__ __nv_bfloat16 g_Ahi[(size_t)Mm*Dd];   // activation hi/lo, K-major
__device__ __nv_bfloat16 g_Alo[(size_t)Mm*Dd];
__device__ __nv_bfloat16 g_Whi[(size_t)Dd*Dd];   // weight^T hi/lo, [N,K] K-major
__device__ __nv_bfloat16 g_Wlo[(size_t)Dd*Dd];
__device__ __nv_bfloat16 g_Qhi[(size_t)Bb*Hh*Ss*DKk];   // [B,H,S,DK]
__device__ __nv_bfloat16 g_Qlo[(size_t)Bb*Hh*Ss*DKk];
__device__ __nv_bfloat16 g_Khi[(size_t)Bb*Hh*Ss*DKk];   // [B,H,S,DK]
__device__ __nv_bfloat16 g_Klo[(size_t)Bb*Hh*Ss*DKk];
__device__ __nv_bfloat16 g_Vthi[(size_t)Bb*Hh*DKk*Ss];  // [B,H,DK,S] (transposed)
__device__ __nv_bfloat16 g_Vtlo[(size_t)Bb*Hh*DKk*Ss];
__device__ __nv_bfloat16 g_Xhi[(size_t)Mm*Dd];   // attention out, [B,S,D]
__device__ __nv_bfloat16 g_Xlo[(size_t)Mm*Dd];

// ---------------- warp-MMA helpers (arch-portable PTX) --------
__device__ __forceinline__ uint32_t smem_u32(const void* p) {
    uint32_t a;
    asm("{ .reg .u64 t; cvta.to.shared.u64 t, %1; cvt.u32.u64 %0, t; }"
        : "=r"(a) : "l"(p));
    return a;
}
__device__ __forceinline__ void ldsm4(uint32_t a, uint32_t& r0, uint32_t& r1,
                                      uint32_t& r2, uint32_t& r3) {
    asm volatile("ldmatrix.sync.aligned.m8n8.x4.shared.b16 {%0,%1,%2,%3}, [%4];"
                 : "=r"(r0), "=r"(r1), "=r"(r2), "=r"(r3) : "r"(a));
}
__device__ __forceinline__ void ldsm2(uint32_t a, uint32_t& r0, uint32_t& r1) {
    asm volatile("ldmatrix.sync.aligned.m8n8.x2.shared.b16 {%0,%1}, [%2];"
                 : "=r"(r0), "=r"(r1) : "r"(a));
}
__device__ __forceinline__ void mma16816(float* c, uint32_t a0, uint32_t a1,
                                         uint32_t a2, uint32_t a3,
                                         uint32_t b0, uint32_t b1) {
    asm volatile(
        "mma.sync.aligned.m16n8k16.row.col.f32.bf16.bf16.f32 "
        "{%0,%1,%2,%3}, {%4,%5,%6,%7}, {%8,%9}, {%0,%1,%2,%3};"
        : "+f"(c[0]), "+f"(c[1]), "+f"(c[2]), "+f"(c[3])
        : "r"(a0), "r"(a1), "r"(a2), "r"(a3), "r"(b0), "r"(b1));
}
// pack two fp32 -> bf16x2 (lo -> low half, hi -> high half)
__device__ __forceinline__ uint32_t packbf(float lo, float hi) {
    uint32_t r;
    asm("cvt.rn.bf16x2.f32 %0, %1, %2;" : "=r"(r) : "f"(hi), "f"(lo));
    return r;
}
__device__ __forceinline__ float bflo_f(uint32_t p) {   // low bf16 -> fp32
    return __uint_as_float(p << 16);
}
__device__ __forceinline__ float bfhi_f(uint32_t p) {   // high bf16 -> fp32
    return __uint_as_float(p & 0xffff0000u);
}

// ---------------------------------------------------------------------------
// fp32 -> bf16 hi/lo split (activations, already K-major)
// ---------------------------------------------------------------------------
__global__ __launch_bounds__(256) void conv_act_kernel(
    const float* __restrict__ in, __nv_bfloat16* __restrict__ hi,
    __nv_bfloat16* __restrict__ lo)
{
    int i = blockIdx.x * blockDim.x + threadIdx.x;   // one float4
    float4 v = ((const float4*)in)[i];
    uint32_t h0 = packbf(v.x, v.y), h1 = packbf(v.z, v.w);
    ((uint32_t*)hi)[i * 2 + 0] = h0;
    ((uint32_t*)hi)[i * 2 + 1] = h1;
    ((uint32_t*)lo)[i * 2 + 0] =
        packbf(v.x - bflo_f(h0), v.y - bfhi_f(h0));
    ((uint32_t*)lo)[i * 2 + 1] =
        packbf(v.z - bflo_f(h1), v.w - bfhi_f(h1));
}

// ---------------------------------------------------------------------------
// weight transpose + split: W[K,N] fp32 -> WT[N,K] bf16 hi/lo
// ---------------------------------------------------------------------------
__global__ __launch_bounds__(256) void conv_wt_kernel(
    const float* __restrict__ W, __nv_bfloat16* __restrict__ hiT,
    __nv_bfloat16* __restrict__ loT)
{
    __shared__ float ts[32][33];
    int tx = threadIdx.x, ty = threadIdx.y;          // 32 x 8
    int bn = blockIdx.x * 32, bk = blockIdx.y * 32;
    #pragma unroll
    for (int r = 0; r < 4; r++)
        ts[ty + r * 8][tx] = W[(size_t)(bk + ty + r * 8) * Dd + bn + tx];
    __syncthreads();
    #pragma unroll
    for (int r = 0; r < 4; r++) {
        float x = ts[tx][ty + r * 8];                // = W[bk+tx][bn+ty+r*8]
        __nv_bfloat16 h = __float2bfloat16(x);
        size_t o = (size_t)(bn + ty + r * 8) * Dd + bk + tx;
        hiT[o] = h;
        loT[o] = __float2bfloat16(x - __bfloat162float(h));
    }
}

// ---------------------------------------------------------------------------
// HMMA bf16x3 GEMM: C = A * W + bias.  A hi/lo [M,K]; W hi/lo [N,K].
// CTA 128x128, K-chunk 32, 8 warps (2m x 4n), warp tile 64x32.
// mode 0: fp32 row-major.   mode 1: bf16 hi/lo -> [B,H,S,DK].
// mode 2: bf16 hi/lo -> [B,H,DK,S] (transposed, for V).
// ---------------------------------------------------------------------------
#define KCH   32
#define NCHUNK (Dd / KCH)          // 32
#define SROW  40                   // padded halves per row
#define ABYTES (128 * SROW * 2)

__global__ __launch_bounds__(256, 1) void hgemm_kernel(
    const __nv_bfloat16* __restrict__ Ahi, const __nv_bfloat16* __restrict__ Alo,
    const __nv_bfloat16* __restrict__ Whi, const __nv_bfloat16* __restrict__ Wlo,
    const float* __restrict__ bias, float* __restrict__ Cf,
    __nv_bfloat16* __restrict__ Chi, __nv_bfloat16* __restrict__ Clo, int mode)
{
    __shared__ __nv_bfloat16 sm[4 * 128 * SROW];

    const int tid  = threadIdx.x;
    const int wid  = tid >> 5, lane = tid & 31;
    const int bm   = blockIdx.y * 128, bn = blockIdx.x * 128;
    const int wm   = wid & 1;
    const int wn   = wid >> 1;

    float c[4][4][4];
    #pragma unroll
    for (int i = 0; i < 4; i++)
        #pragma unroll
        for (int j = 0; j < 4; j++)
            #pragma unroll
            for (int r = 0; r < 4; r++) c[i][j][r] = 0.f;

    const int u0 = tid, u1 = tid + 256;
    const int r0 = u0 >> 2, q0 = (u0 & 3) * 8;
    const int r1 = u1 >> 2, q1 = (u1 & 3) * 8;

    uint4 ld[8];
    #define LOAD_CHUNK(cc) do {                                                 \
        const int k0_ = (cc) * KCH;                                             \
        ld[0] = *(const uint4*)&Ahi[(size_t)(bm + r0) * Dd + k0_ + q0];         \
        ld[1] = *(const uint4*)&Ahi[(size_t)(bm + r1) * Dd + k0_ + q1];         \
        ld[2] = *(const uint4*)&Alo[(size_t)(bm + r0) * Dd + k0_ + q0];         \
        ld[3] = *(const uint4*)&Alo[(size_t)(bm + r1) * Dd + k0_ + q1];         \
        ld[4] = *(const uint4*)&Whi[(size_t)(bn + r0) * Dd + k0_ + q0];         \
        ld[5] = *(const uint4*)&Whi[(size_t)(bn + r1) * Dd + k0_ + q1];         \
        ld[6] = *(const uint4*)&Wlo[(size_t)(bn + r0) * Dd + k0_ + q0];         \
        ld[7] = *(const uint4*)&Wlo[(size_t)(bn + r1) * Dd + k0_ + q1];         \
    } while (0)
    #define STORE_CHUNK() do {                                                  \
        *(uint4*)&sm[0 * 128 * SROW + r0 * SROW + q0] = ld[0];                  \
        *(uint4*)&sm[0 * 128 * SROW + r1 * SROW + q1] = ld[1];                  \
        *(uint4*)&sm[1 * 128 * SROW + r0 * SROW + q0] = ld[2];                  \
        *(uint4*)&sm[1 * 128 * SROW + r1 * SROW + q1] = ld[3];                  \
        *(uint4*)&sm[2 * 128 * SROW + r0 * SROW + q0] = ld[4];                  \
        *(uint4*)&sm[2 * 128 * SROW + r1 * SROW + q1] = ld[5];                  \
        *(uint4*)&sm[3 * 128 * SROW + r0 * SROW + q0] = ld[6];                  \
        *(uint4*)&sm[3 * 128 * SROW + r1 * SROW + q1] = ld[7];                  \
    } while (0)

    const uint32_t sb = smem_u32(sm);
    const uint32_t aoff =
        sb + (uint32_t)(((wm * 64 + (lane & 15)) * SROW + (lane >> 4) * 8) * 2);
    const uint32_t boff =
        sb + (uint32_t)(((wn * 32 + (lane & 7)) * SROW + ((lane >> 3) & 1) * 8) * 2);

    LOAD_CHUNK(0);
    STORE_CHUNK();

    for (int cc = 0; cc < NCHUNK; cc++) {
        __syncthreads();
        if (cc + 1 < NCHUNK) LOAD_CHUNK(cc + 1);

        #pragma unroll
        for (int pass = 0; pass < 3; pass++) {
            const uint32_t Ab  = aoff + (pass == 2 ? ABYTES : 0);
            const uint32_t Bbp = boff + 2 * ABYTES + (pass == 1 ? ABYTES : 0);
            #pragma unroll
            for (int ks = 0; ks < 2; ks++) {
                uint32_t a[4][4], b[4][2];
                #pragma unroll
                for (int mi = 0; mi < 4; mi++)
                    ldsm4(Ab + mi * (16 * SROW * 2) + ks * 32,
                          a[mi][0], a[mi][1], a[mi][2], a[mi][3]);
                #pragma unroll
                for (int ni = 0; ni < 4; ni++)
                    ldsm2(Bbp + ni * (8 * SROW * 2) + ks * 32, b[ni][0], b[ni][1]);
                #pragma unroll
                for (int mi = 0; mi < 4; mi++)
                    #pragma unroll
                    for (int ni = 0; ni < 4; ni++)
                        mma16816(c[mi][ni], a[mi][0], a[mi][1], a[mi][2], a[mi][3],
                                 b[ni][0], b[ni][1]);
            }
        }
        __syncthreads();
        if (cc + 1 < NCHUNK) STORE_CHUNK();
    }

    // ---- epilogue ----
    const int mrow0 = bm + wm * 64 + (lane >> 2);
    const int ncol0 = bn + wn * 32 + (lane & 3) * 2;
    #pragma unroll
    for (int mi = 0; mi < 4; mi++) {
        #pragma unroll
        for (int h2 = 0; h2 < 2; h2++) {
            const int m = mrow0 + mi * 16 + h2 * 8;
            const int b = m >> 11, s = m & 2047;
            #pragma unroll
            for (int ni = 0; ni < 4; ni++) {
                const int n = ncol0 + ni * 8;
                float v0 = c[mi][ni][h2 * 2 + 0] + bias[n];
                float v1 = c[mi][ni][h2 * 2 + 1] + bias[n + 1];
                if (mode == 0) {
                    float2 v; v.x = v0; v.y = v1;
                    *(float2*)&Cf[(size_t)m * Dd + n] = v;
                } else {
                    const int h = n >> 6, dk = n & 63;
                    uint32_t hp = packbf(v0, v1);
                    uint32_t lp = packbf(v0 - bflo_f(hp), v1 - bfhi_f(hp));
                    if (mode == 1) {
                        size_t o = (((size_t)(b * Hh + h)) * Ss + s) * DKk + dk;
                        *(uint32_t*)&Chi[o] = hp;
                        *(uint32_t*)&Clo[o] = lp;
                    } else {
                        size_t o = (((size_t)(b * Hh + h)) * DKk + dk) * Ss + s;
                        Chi[o]      = __ushort_as_bfloat16((uint16_t)(hp & 0xffff));
                        Chi[o + Ss] = __ushort_as_bfloat16((uint16_t)(hp >> 16));
                        Clo[o]      = __ushort_as_bfloat16((uint16_t)(lp & 0xffff));
                        Clo[o + Ss] = __ushort_as_bfloat16((uint16_t)(lp >> 16));
                    }
                }
            }
        }
    }
}

// ---------------------------------------------------------------------------
// HMMA flash attention, bf16x3 split precision, causal.
// CTA: 64 query rows of one (b,h); 4 warps x 16 rows. KV tiles of 64 keys.
// QK^T = Qh*Kh + Qh*Kl + Ql*Kh ; PV = Ph*Vh + Ph*Vl + Pl*Vh (P split in regs).
// Smem rows padded to 72 halves (144B) -> ldmatrix conflict-free.
// ---------------------------------------------------------------------------
#define APAD 72
#define A_TILE (64 * APAD)             // halves per tile
#define OFF_QH 0
#define OFF_QL (1 * A_TILE)
#define OFF_KH (2 * A_TILE)
#define OFF_KL (3 * A_TILE)
#define OFF_VH (4 * A_TILE)
#define OFF_VL (5 * A_TILE)
#define ATTN_SMEM (6 * A_TILE * 2)     // 55296 B

__global__ __launch_bounds__(128, 1) void attn_mma_kernel(
    const __nv_bfloat16* __restrict__ Qhi, const __nv_bfloat16* __restrict__ Qlo,
    const __nv_bfloat16* __restrict__ Khi, const __nv_bfloat16* __restrict__ Klo,
    const __nv_bfloat16* __restrict__ Vthi, const __nv_bfloat16* __restrict__ Vtlo,
    __nv_bfloat16* __restrict__ Xhi, __nv_bfloat16* __restrict__ Xlo)
{
    extern __shared__ __nv_bfloat16 smA[];
    const int tid  = threadIdx.x;
    const int w    = tid >> 5, lane = tid & 31;
    const int bh   = blockIdx.y;
    const int iq   = gridDim.x - 1 - blockIdx.x;   // long CTAs first
    const size_t baseQK = (size_t)bh * Ss * DKk;
    const size_t baseV  = (size_t)bh * DKk * Ss;

    // ---- load Q tile (64x64 hi/lo) ----
    {
        const __nv_bfloat16* Qh_g = Qhi + baseQK + (size_t)iq * 64 * DKk;
        const __nv_bfloat16* Ql_g = Qlo + baseQK + (size_t)iq * 64 * DKk;
        #pragma unroll
        for (int t = 0; t < 4; t++) {
            int idx = tid + t * 128;          // 0..511
            int row = idx >> 3, cu = (idx & 7) * 8;
            *(uint4*)&smA[OFF_QH + row * APAD + cu] = *(const uint4*)&Qh_g[row * DKk + cu];
            *(uint4*)&smA[OFF_QL + row * APAD + cu] = *(const uint4*)&Ql_g[row * DKk + cu];
        }
    }
    __syncthreads();

    const uint32_t sb = smem_u32(smA);
    // A-fragment address (warp's 16 rows), per array
    const uint32_t a_off = (uint32_t)(((w * 16 + (lane & 15)) * APAD + (lane >> 4) * 8) * 2);
    // B-fragment ldsm4 address (16 rows of tile)
    const uint32_t b_off = (uint32_t)((((lane & 15)) * APAD + (lane >> 4) * 8) * 2);

    // hold Q fragments (4 k-steps x 4 regs, hi and lo)
    uint32_t qh[4][4], ql[4][4];
    #pragma unroll
    for (int kk = 0; kk < 4; kk++) {
        ldsm4(sb + OFF_QH * 2 + a_off + kk * 32, qh[kk][0], qh[kk][1], qh[kk][2], qh[kk][3]);
        ldsm4(sb + OFF_QL * 2 + a_off + kk * 32, ql[kk][0], ql[kk][1], ql[kk][2], ql[kk][3]);
    }

    float o[8][4];
    #pragma unroll
    for (int i = 0; i < 8; i++)
        #pragma unroll
        for (int r = 0; r < 4; r++) o[i][r] = 0.f;
    float m_lo = -1e30f, m_hi = -1e30f, l_lo = 0.f, l_hi = 0.f;

    for (int j = 0; j <= iq; j++) {
        __syncthreads();   // previous tile fully consumed
        {
            const __nv_bfloat16* Kh_g = Khi + baseQK + (size_t)j * 64 * DKk;
            const __nv_bfloat16* Kl_g = Klo + baseQK + (size_t)j * 64 * DKk;
            const __nv_bfloat16* Vh_g = Vthi + baseV + (size_t)j * 64;
            const __nv_bfloat16* Vl_g = Vtlo + baseV + (size_t)j * 64;
            #pragma unroll
            for (int t = 0; t < 4; t++) {
                int idx = tid + t * 128;
                int row = idx >> 3, cu = (idx & 7) * 8;
                *(uint4*)&smA[OFF_KH + row * APAD + cu] = *(const uint4*)&Kh_g[row * DKk + cu];
                *(uint4*)&smA[OFF_KL + row * APAD + cu] = *(const uint4*)&Kl_g[row * DKk + cu];
                *(uint4*)&smA[OFF_VH + row * APAD + cu] = *(const uint4*)&Vh_g[(size_t)row * Ss + cu];
                *(uint4*)&smA[OFF_VL + row * APAD + cu] = *(const uint4*)&Vl_g[(size_t)row * Ss + cu];
            }
        }
        __syncthreads();

        // ---- scores S = Q K^T (3-term) ----
        float s[8][4];
        #pragma unroll
        for (int i = 0; i < 8; i++)
            #pragma unroll
            for (int r = 0; r < 4; r++) s[i][r] = 0.f;

        #pragma unroll
        for (int kk = 0; kk < 4; kk++) {
            uint32_t kh[8][2], kl[8][2];
            #pragma unroll
            for (int np = 0; np < 4; np++) {
                uint32_t t0, t1, t2, t3;
                ldsm4(sb + OFF_KH * 2 + b_off + np * (16 * APAD * 2) + kk * 32, t0, t1, t2, t3);
                kh[2 * np][0] = t0; kh[2 * np][1] = t2;
                kh[2 * np + 1][0] = t1; kh[2 * np + 1][1] = t3;
                ldsm4(sb + OFF_KL * 2 + b_off + np * (16 * APAD * 2) + kk * 32, t0, t1, t2, t3);
                kl[2 * np][0] = t0; kl[2 * np][1] = t2;
                kl[2 * np + 1][0] = t1; kl[2 * np + 1][1] = t3;
            }
            #pragma unroll
            for (int ni = 0; ni < 8; ni++)
                mma16816(s[ni], qh[kk][0], qh[kk][1], qh[kk][2], qh[kk][3],
                         kh[ni][0], kh[ni][1]);
            #pragma unroll
            for (int ni = 0; ni < 8; ni++)
                mma16816(s[ni], qh[kk][0], qh[kk][1], qh[kk][2], qh[kk][3],
                         kl[ni][0], kl[ni][1]);
            #pragma unroll
            for (int ni = 0; ni < 8; ni++)
                mma16816(s[ni], ql[kk][0], ql[kk][1], ql[kk][2], ql[kk][3],
                         kh[ni][0], kh[ni][1]);
        }

        // ---- scale + causal mask (diagonal tile only) ----
        #pragma unroll
        for (int ni = 0; ni < 8; ni++)
            #pragma unroll
            for (int r = 0; r < 4; r++) s[ni][r] *= 0.125f;
        if (j == iq) {
            const int rlo = w * 16 + (lane >> 2), rhi = rlo + 8;
            #pragma unroll
            for (int ni = 0; ni < 8; ni++) {
                const int c0 = ni * 8 + (lane & 3) * 2;
                if (c0 > rlo)     s[ni][0] = -1e30f;
                if (c0 + 1 > rlo) s[ni][1] = -1e30f;
                if (c0 > rhi)     s[ni][2] = -1e30f;
                if (c0 + 1 > rhi) s[ni][3] = -1e30f;
            }
        }

        // ---- online softmax (fp32) ----
        float mx_lo = s[0][0], mx_hi = s[0][2];
        #pragma unroll
        for (int ni = 0; ni < 8; ni++) {
            mx_lo = fmaxf(mx_lo, fmaxf(s[ni][0], s[ni][1]));
            mx_hi = fmaxf(mx_hi, fmaxf(s[ni][2], s[ni][3]));
        }
        mx_lo = fmaxf(mx_lo, __shfl_xor_sync(0xffffffffu, mx_lo, 1));
        mx_lo = fmaxf(mx_lo, __shfl_xor_sync(0xffffffffu, mx_lo, 2));
        mx_hi = fmaxf(mx_hi, __shfl_xor_sync(0xffffffffu, mx_hi, 1));
        mx_hi = fmaxf(mx_hi, __shfl_xor_sync(0xffffffffu, mx_hi, 2));
        const float mn_lo = fmaxf(m_lo, mx_lo), mn_hi = fmaxf(m_hi, mx_hi);
        const float al_lo = __expf(m_lo - mn_lo), al_hi = __expf(m_hi - mn_hi);

        uint32_t ph[8][2], pl[8][2];
        float sum_lo = 0.f, sum_hi = 0.f;
        #pragma unroll
        for (int ni = 0; ni < 8; ni++) {
            float p0 = __expf(s[ni][0] - mn_lo);
            float p1 = __expf(s[ni][1] - mn_lo);
            float p2 = __expf(s[ni][2] - mn_hi);
            float p3 = __expf(s[ni][3] - mn_hi);
            sum_lo += p0 + p1; sum_hi += p2 + p3;
            uint32_t h01 = packbf(p0, p1), h23 = packbf(p2, p3);
            ph[ni][0] = h01; ph[ni][1] = h23;
            pl[ni][0] = packbf(p0 - bflo_f(h01), p1 - bfhi_f(h01));
            pl[ni][1] = packbf(p2 - bflo_f(h23), p3 - bfhi_f(h23));
        }
        sum_lo += __shfl_xor_sync(0xffffffffu, sum_lo, 1);
        sum_lo += __shfl_xor_sync(0xffffffffu, sum_lo, 2);
        sum_hi += __shfl_xor_sync(0xffffffffu, sum_hi, 1);
        sum_hi += __shfl_xor_sync(0xffffffffu, sum_hi, 2);
        l_lo = l_lo * al_lo + sum_lo;  m_lo = mn_lo;
        l_hi = l_hi * al_hi + sum_hi;  m_hi = mn_hi;
        #pragma unroll
        for (int ni = 0; ni < 8; ni++) {
            o[ni][0] *= al_lo; o[ni][1] *= al_lo;
            o[ni][2] *= al_hi; o[ni][3] *= al_hi;
        }

        // ---- O += P V (3-term) ----
        #pragma unroll
        for (int kk = 0; kk < 4; kk++) {
            uint32_t vh[8][2], vl[8][2];
            #pragma unroll
            for (int np = 0; np < 4; np++) {
                uint32_t t0, t1, t2, t3;
                ldsm4(sb + OFF_VH * 2 + b_off + np * (16 * APAD * 2) + kk * 32, t0, t1, t2, t3);
                vh[2 * np][0] = t0; vh[2 * np][1] = t2;
                vh[2 * np + 1][0] = t1; vh[2 * np + 1][1] = t3;
                ldsm4(sb + OFF_VL * 2 + b_off + np * (16 * APAD * 2) + kk * 32, t0, t1, t2, t3);
                vl[2 * np][0] = t0; vl[2 * np][1] = t2;
                vl[2 * np + 1][0] = t1; vl[2 * np + 1][1] = t3;
            }
            const uint32_t pa0 = ph[2 * kk][0], pa1 = ph[2 * kk][1];
            const uint32_t pa2 = ph[2 * kk + 1][0], pa3 = ph[2 * kk + 1][1];
            const uint32_t qa0 = pl[2 * kk][0], qa1 = pl[2 * kk][1];
            const uint32_t qa2 = pl[2 * kk + 1][0], qa3 = pl[2 * kk + 1][1];
            #pragma unroll
            for (int ni = 0; ni < 8; ni++)
                mma16816(o[ni], pa0, pa1, pa2, pa3, vh[ni][0], vh[ni][1]);
            #pragma unroll
            for (int ni = 0; ni < 8; ni++)
                mma16816(o[ni], pa0, pa1, pa2, pa3, vl[ni][0], vl[ni][1]);
            #pragma unroll
            for (int ni = 0; ni < 8; ni++)
                mma16816(o[ni], qa0, qa1, qa2, qa3, vh[ni][0], vh[ni][1]);
        }
    }

    // ---- epilogue: X[b, s, h*64+dk] as bf16 hi/lo ----
    const float inv_lo = 1.f / l_lo, inv_hi = 1.f / l_hi;
    const int b = bh >> 4, h = bh & 15;
    const int s_lo = iq * 64 + w * 16 + (lane >> 2);
    const int s_hi = s_lo + 8;
    #pragma unroll
    for (int ni = 0; ni < 8; ni++) {
        const int dk = ni * 8 + (lane & 3) * 2;
        const size_t o_lo = ((size_t)(b * Ss + s_lo)) * Dd + h * DKk + dk;
        const size_t o_hi = ((size_t)(b * Ss + s_hi)) * Dd + h * DKk + dk;
        float v0 = o[ni][0] * inv_lo, v1 = o[ni][1] * inv_lo;
        float v2 = o[ni][2] * inv_hi, v3 = o[ni][3] * inv_hi;
        uint32_t hp0 = packbf(v0, v1), hp1 = packbf(v2, v3);
        *(uint32_t*)&Xhi[o_lo] = hp0;
        *(uint32_t*)&Xhi[o_hi] = hp1;
        *(uint32_t*)&Xlo[o_lo] = packbf(v0 - bflo_f(hp0), v1 - bfhi_f(hp0));
        *(uint32_t*)&Xlo[o_hi] = packbf(v2 - bflo_f(hp1), v3 - bfhi_f(hp1));
    }
}

// ---------------------------------------------------------------------------
extern "C" void kernel_launch(void* const* d_in, const int* in_sizes, int n_in,
                              void* d_out, int out_size)
{
    const float* q   = (const float*)d_in[0];
    const float* k   = (const float*)d_in[1];
    const float* v   = (const float*)d_in[2];
    // d_in[3] = causal mask (int32) — causality computed analytically
    const float* w_q = (const float*)d_in[4];
    const float* b_q = (const float*)d_in[5];
    const float* w_k = (const float*)d_in[6];
    const float* b_k = (const float*)d_in[7];
    const float* w_v = (const float*)d_in[8];
    const float* b_v = (const float*)d_in[9];
    const float* w_o = (const float*)d_in[10];
    const float* b_o = (const float*)d_in[11];
    float* out = (float*)d_out;

    __nv_bfloat16 *pAhi, *pAlo, *pWhi, *pWlo;
    __nv_bfloat16 *pQh, *pQl, *pKh, *pKl, *pVh, *pVl, *pXh, *pXl;
    cudaGetSymbolAddress((void**)&pAhi, g_Ahi);
    cudaGetSymbolAddress((void**)&pAlo, g_Alo);
    cudaGetSymbolAddress((void**)&pWhi, g_Whi);
    cudaGetSymbolAddress((void**)&pWlo, g_Wlo);
    cudaGetSymbolAddress((void**)&pQh,  g_Qhi);
    cudaGetSymbolAddress((void**)&pQl,  g_Qlo);
    cudaGetSymbolAddress((void**)&pKh,  g_Khi);
    cudaGetSymbolAddress((void**)&pKl,  g_Klo);
    cudaGetSymbolAddress((void**)&pVh,  g_Vthi);
    cudaGetSymbolAddress((void**)&pVl,  g_Vtlo);
    cudaGetSymbolAddress((void**)&pXh,  g_Xhi);
    cudaGetSymbolAddress((void**)&pXl,  g_Xlo);

    cudaFuncSetAttribute(attn_mma_kernel,
                         cudaFuncAttributeMaxDynamicSharedMemorySize, ATTN_SMEM);

    const int conv_act_blocks = (Mm * Dd / 4) / 256;   // 4096
    dim3 wt_grid(32, 32), wt_block(32, 8);
    dim3 gemm_grid(Dd / 128, Mm / 128);                // (8, 32)

    conv_act_kernel<<<conv_act_blocks, 256>>>(q, pAhi, pAlo);
    conv_wt_kernel<<<wt_grid, wt_block>>>(w_q, pWhi, pWlo);
    hgemm_kernel<<<gemm_grid, 256>>>(pAhi, pAlo, pWhi, pWlo, b_q, nullptr, pQh, pQl, 1);

    conv_act_kernel<<<conv_act_blocks, 256>>>(k, pAhi, pAlo);
    conv_wt_kernel<<<wt_grid, wt_block>>>(w_k, pWhi, pWlo);
    hgemm_kernel<<<gemm_grid, 256>>>(pAhi, pAlo, pWhi, pWlo, b_k, nullptr, pKh, pKl, 1);

    conv_act_kernel<<<conv_act_blocks, 256>>>(v, pAhi, pAlo);
    conv_wt_kernel<<<wt_grid, wt_block>>>(w_v, pWhi, pWlo);
    hgemm_kernel<<<gemm_grid, 256>>>(pAhi, pAlo, pWhi, pWlo, b_v, nullptr, pVh, pVl, 2);

    dim3 agrid(Ss / 64, Bb * Hh);                      // (32, 32)
    attn_mma_kernel<<<agrid, 128, ATTN_SMEM>>>(pQh, pQl, pKh, pKl, pVh, pVl, pXh, pXl);

    conv_wt_kernel<<<wt_grid, wt_block>>>(w_o, pWhi, pWlo);
    hgemm_kernel<<<gemm_grid, 256>>>(pXh, pXl, pWhi, pWlo, b_o, out, nullptr, nullptr, 0);
}

// round 7
// speedup vs baseline: 3.0865x; 1.1422x over previous
#include <cuda_runtime.h>
#include <cuda_bf16.h>
#include <cstdint>

#define Bb  2
#define Ss  2048
#define Dd  1024
#define Hh  16
#define DKk 64
#define Mm  (Bb*Ss)

// ---------------- scratch (allocation-free: device globals) ----------------
__device__ __nv_bfloat16 g_A0hi[(size_t)Mm*Dd], g_A0lo[(size_t)Mm*Dd];
__device__ __nv_bfloat16 g_A1hi[(size_t)Mm*Dd], g_A1lo[(size_t)Mm*Dd];
__device__ __nv_bfloat16 g_A2hi[(size_t)Mm*Dd], g_A2lo[(size_t)Mm*Dd];
__device__ __nv_bfloat16 g_W0hi[(size_t)Dd*Dd], g_W0lo[(size_t)Dd*Dd];
__device__ __nv_bfloat16 g_W1hi[(size_t)Dd*Dd], g_W1lo[(size_t)Dd*Dd];
__device__ __nv_bfloat16 g_W2hi[(size_t)Dd*Dd], g_W2lo[(size_t)Dd*Dd];
__device__ __nv_bfloat16 g_W3hi[(size_t)Dd*Dd], g_W3lo[(size_t)Dd*Dd];
__device__ __nv_bfloat16 g_Qhi[(size_t)Bb*Hh*Ss*DKk], g_Qlo[(size_t)Bb*Hh*Ss*DKk];
__device__ __nv_bfloat16 g_Khi[(size_t)Bb*Hh*Ss*DKk], g_Klo[(size_t)Bb*Hh*Ss*DKk];
__device__ __nv_bfloat16 g_Vthi[(size_t)Bb*Hh*DKk*Ss], g_Vtlo[(size_t)Bb*Hh*DKk*Ss];
__device__ __nv_bfloat16 g_Xhi[(size_t)Mm*Dd], g_Xlo[(size_t)Mm*Dd];

// ---------------- helpers (arch-portable PTX) --------
__device__ __forceinline__ uint32_t smem_u32(const void* p) {
    uint32_t a;
    asm("{ .reg .u64 t; cvta.to.shared.u64 t, %1; cvt.u32.u64 %0, t; }"
        : "=r"(a) : "l"(p));
    return a;
}
__device__ __forceinline__ void ldsm4(uint32_t a, uint32_t& r0, uint32_t& r1,
                                      uint32_t& r2, uint32_t& r3) {
    asm volatile("ldmatrix.sync.aligned.m8n8.x4.shared.b16 {%0,%1,%2,%3}, [%4];"
                 : "=r"(r0), "=r"(r1), "=r"(r2), "=r"(r3) : "r"(a));
}
__device__ __forceinline__ void ldsm2(uint32_t a, uint32_t& r0, uint32_t& r1) {
    asm volatile("ldmatrix.sync.aligned.m8n8.x2.shared.b16 {%0,%1}, [%2];"
                 : "=r"(r0), "=r"(r1) : "r"(a));
}
__device__ __forceinline__ void mma16816(float* c, uint32_t a0, uint32_t a1,
                                         uint32_t a2, uint32_t a3,
                                         uint32_t b0, uint32_t b1) {
    asm volatile(
        "mma.sync.aligned.m16n8k16.row.col.f32.bf16.bf16.f32 "
        "{%0,%1,%2,%3}, {%4,%5,%6,%7}, {%8,%9}, {%0,%1,%2,%3};"
        : "+f"(c[0]), "+f"(c[1]), "+f"(c[2]), "+f"(c[3])
        : "r"(a0), "r"(a1), "r"(a2), "r"(a3), "r"(b0), "r"(b1));
}
__device__ __forceinline__ uint32_t packbf(float lo, float hi) {
    uint32_t r;
    asm("cvt.rn.bf16x2.f32 %0, %1, %2;" : "=r"(r) : "f"(hi), "f"(lo));
    return r;
}
__device__ __forceinline__ float bflo_f(uint32_t p) { return __uint_as_float(p << 16); }
__device__ __forceinline__ float bfhi_f(uint32_t p) { return __uint_as_float(p & 0xffff0000u); }

__device__ __forceinline__ void cpasync16(uint32_t saddr, const void* g) {
    asm volatile("cp.async.ca.shared.global [%0], [%1], 16;"
                 :: "r"(saddr), "l"(g) : "memory");
}
#define CP_COMMIT() asm volatile("cp.async.commit_group;" ::: "memory")
#define CP_WAIT0()  asm volatile("cp.async.wait_group 0;" ::: "memory")

// ---------------------------------------------------------------------------
// merged fp32 -> bf16 hi/lo splits for q,k,v activations
// ---------------------------------------------------------------------------
__global__ __launch_bounds__(256) void conv_act_all(
    const float* __restrict__ q, const float* __restrict__ k,
    const float* __restrict__ v)
{
    const float* src = (blockIdx.y == 0) ? q : (blockIdx.y == 1) ? k : v;
    __nv_bfloat16* hi = (blockIdx.y == 0) ? g_A0hi : (blockIdx.y == 1) ? g_A1hi : g_A2hi;
    __nv_bfloat16* lo = (blockIdx.y == 0) ? g_A0lo : (blockIdx.y == 1) ? g_A1lo : g_A2lo;
    int i = blockIdx.x * blockDim.x + threadIdx.x;
    float4 vv = ((const float4*)src)[i];
    uint32_t h0 = packbf(vv.x, vv.y), h1 = packbf(vv.z, vv.w);
    ((uint32_t*)hi)[i * 2 + 0] = h0;
    ((uint32_t*)hi)[i * 2 + 1] = h1;
    ((uint32_t*)lo)[i * 2 + 0] = packbf(vv.x - bflo_f(h0), vv.y - bfhi_f(h0));
    ((uint32_t*)lo)[i * 2 + 1] = packbf(vv.z - bflo_f(h1), vv.w - bfhi_f(h1));
}

// ---------------------------------------------------------------------------
// merged weight transpose + split: W[K,N] -> WT[N,K] hi/lo, 4 weights
// ---------------------------------------------------------------------------
__global__ __launch_bounds__(256) void conv_wt_all(
    const float* __restrict__ w0, const float* __restrict__ w1,
    const float* __restrict__ w2, const float* __restrict__ w3)
{
    __shared__ float ts[32][33];
    const int z = blockIdx.z;
    const float* W = (z == 0) ? w0 : (z == 1) ? w1 : (z == 2) ? w2 : w3;
    __nv_bfloat16* hiT = (z == 0) ? g_W0hi : (z == 1) ? g_W1hi : (z == 2) ? g_W2hi : g_W3hi;
    __nv_bfloat16* loT = (z == 0) ? g_W0lo : (z == 1) ? g_W1lo : (z == 2) ? g_W2lo : g_W3lo;
    int tx = threadIdx.x, ty = threadIdx.y;          // 32 x 8
    int bn = blockIdx.x * 32, bk = blockIdx.y * 32;
    #pragma unroll
    for (int r = 0; r < 4; r++)
        ts[ty + r * 8][tx] = W[(size_t)(bk + ty + r * 8) * Dd + bn + tx];
    __syncthreads();
    #pragma unroll
    for (int r = 0; r < 4; r++) {
        float x = ts[tx][ty + r * 8];
        __nv_bfloat16 h = __float2bfloat16(x);
        size_t o = (size_t)(bn + ty + r * 8) * Dd + bk + tx;
        hiT[o] = h;
        loT[o] = __float2bfloat16(x - __bfloat162float(h));
    }
}

// ---------------------------------------------------------------------------
// HMMA bf16x3 GEMM body: cp.async double-buffered.
// CTA 128x128, K-chunk 32, 8 warps (2m x 4n), warp tile 64x32.
// mode 0: fp32 row-major; 1: bf16 hi/lo [B,H,S,DK]; 2: bf16 hi/lo [B,H,DK,S].
// ---------------------------------------------------------------------------
#define KCH   32
#define NCHUNK (Dd / KCH)          // 32
#define SROW  40                   // padded halves per row
#define ABYTES (128 * SROW * 2)    // 10240 B per array
#define BUFB  (4 * ABYTES)         // 40960 B per stage
#define GSMEM (2 * BUFB)           // 81920 B

__device__ __forceinline__ void hgemm_body(
    const __nv_bfloat16* __restrict__ Ahi, const __nv_bfloat16* __restrict__ Alo,
    const __nv_bfloat16* __restrict__ Whi, const __nv_bfloat16* __restrict__ Wlo,
    const float* __restrict__ bias, float* __restrict__ Cf,
    __nv_bfloat16* __restrict__ Chi, __nv_bfloat16* __restrict__ Clo,
    int mode, __nv_bfloat16* sm)
{
    const int tid  = threadIdx.x;
    const int wid  = tid >> 5, lane = tid & 31;
    const int bm   = blockIdx.y * 128, bn = blockIdx.x * 128;
    const int wm   = wid & 1, wn = wid >> 1;

    float c[4][4][4];
    #pragma unroll
    for (int i = 0; i < 4; i++)
        #pragma unroll
        for (int j = 0; j < 4; j++)
            #pragma unroll
            for (int r = 0; r < 4; r++) c[i][j][r] = 0.f;

    const int r0 = tid >> 2,         q0 = (tid & 3) * 8;
    const int r1 = (tid + 256) >> 2, q1 = ((tid + 256) & 3) * 8;
    const uint32_t sb = smem_u32(sm);

    #define ISSUE_CHUNK(cc, base) do {                                          \
        const int k0_ = (cc) * KCH;                                             \
        cpasync16((base) + (uint32_t)((0 * 128 * SROW + r0 * SROW + q0) * 2),   \
                  &Ahi[(size_t)(bm + r0) * Dd + k0_ + q0]);                     \
        cpasync16((base) + (uint32_t)((0 * 128 * SROW + r1 * SROW + q1) * 2),   \
                  &Ahi[(size_t)(bm + r1) * Dd + k0_ + q1]);                     \
        cpasync16((base) + (uint32_t)((1 * 128 * SROW + r0 * SROW + q0) * 2),   \
                  &Alo[(size_t)(bm + r0) * Dd + k0_ + q0]);                     \
        cpasync16((base) + (uint32_t)((1 * 128 * SROW + r1 * SROW + q1) * 2),   \
                  &Alo[(size_t)(bm + r1) * Dd + k0_ + q1]);                     \
        cpasync16((base) + (uint32_t)((2 * 128 * SROW + r0 * SROW + q0) * 2),   \
                  &Whi[(size_t)(bn + r0) * Dd + k0_ + q0]);                     \
        cpasync16((base) + (uint32_t)((2 * 128 * SROW + r1 * SROW + q1) * 2),   \
                  &Whi[(size_t)(bn + r1) * Dd + k0_ + q1]);                     \
        cpasync16((base) + (uint32_t)((3 * 128 * SROW + r0 * SROW + q0) * 2),   \
                  &Wlo[(size_t)(bn + r0) * Dd + k0_ + q0]);                     \
        cpasync16((base) + (uint32_t)((3 * 128 * SROW + r1 * SROW + q1) * 2),   \
                  &Wlo[(size_t)(bn + r1) * Dd + k0_ + q1]);                     \
        CP_COMMIT();                                                            \
    } while (0)

    const uint32_t aoff =
        (uint32_t)(((wm * 64 + (lane & 15)) * SROW + (lane >> 4) * 8) * 2);
    const uint32_t boff =
        (uint32_t)(((wn * 32 + (lane & 7)) * SROW + ((lane >> 3) & 1) * 8) * 2);

    ISSUE_CHUNK(0, sb);

    for (int cc = 0; cc < NCHUNK; cc++) {
        CP_WAIT0();
        __syncthreads();
        if (cc + 1 < NCHUNK)
            ISSUE_CHUNK(cc + 1, sb + (uint32_t)((cc + 1) & 1) * BUFB);

        const uint32_t bufb = sb + (uint32_t)(cc & 1) * BUFB;
        #pragma unroll
        for (int pass = 0; pass < 3; pass++) {
            const uint32_t Ab  = bufb + aoff + (pass == 2 ? (uint32_t)ABYTES : 0u);
            const uint32_t Bbp = bufb + boff + 2u * ABYTES + (pass == 1 ? (uint32_t)ABYTES : 0u);
            #pragma unroll
            for (int ks = 0; ks < 2; ks++) {
                uint32_t a[4][4], b[4][2];
                #pragma unroll
                for (int mi = 0; mi < 4; mi++)
                    ldsm4(Ab + mi * (16 * SROW * 2) + ks * 32,
                          a[mi][0], a[mi][1], a[mi][2], a[mi][3]);
                #pragma unroll
                for (int ni = 0; ni < 4; ni++)
                    ldsm2(Bbp + ni * (8 * SROW * 2) + ks * 32, b[ni][0], b[ni][1]);
                #pragma unroll
                for (int mi = 0; mi < 4; mi++)
                    #pragma unroll
                    for (int ni = 0; ni < 4; ni++)
                        mma16816(c[mi][ni], a[mi][0], a[mi][1], a[mi][2], a[mi][3],
                                 b[ni][0], b[ni][1]);
            }
        }
    }

    // ---- epilogue ----
    const int mrow0 = bm + wm * 64 + (lane >> 2);
    const int ncol0 = bn + wn * 32 + (lane & 3) * 2;
    #pragma unroll
    for (int mi = 0; mi < 4; mi++) {
        #pragma unroll
        for (int h2 = 0; h2 < 2; h2++) {
            const int m = mrow0 + mi * 16 + h2 * 8;
            const int b = m >> 11, s = m & 2047;
            #pragma unroll
            for (int ni = 0; ni < 4; ni++) {
                const int n = ncol0 + ni * 8;
                float v0 = c[mi][ni][h2 * 2 + 0] + bias[n];
                float v1 = c[mi][ni][h2 * 2 + 1] + bias[n + 1];
                if (mode == 0) {
                    float2 v; v.x = v0; v.y = v1;
                    *(float2*)&Cf[(size_t)m * Dd + n] = v;
                } else {
                    const int h = n >> 6, dk = n & 63;
                    uint32_t hp = packbf(v0, v1);
                    uint32_t lp = packbf(v0 - bflo_f(hp), v1 - bfhi_f(hp));
                    if (mode == 1) {
                        size_t o = (((size_t)(b * Hh + h)) * Ss + s) * DKk + dk;
                        *(uint32_t*)&Chi[o] = hp;
                        *(uint32_t*)&Clo[o] = lp;
                    } else {
                        size_t o = (((size_t)(b * Hh + h)) * DKk + dk) * Ss + s;
                        Chi[o]      = __ushort_as_bfloat16((uint16_t)(hp & 0xffff));
                        Chi[o + Ss] = __ushort_as_bfloat16((uint16_t)(hp >> 16));
                        Clo[o]      = __ushort_as_bfloat16((uint16_t)(lp & 0xffff));
                        Clo[o + Ss] = __ushort_as_bfloat16((uint16_t)(lp >> 16));
                    }
                }
            }
        }
    }
    #undef ISSUE_CHUNK
}

// batched QKV projections: blockIdx.z selects {Q, K, V}
__global__ __launch_bounds__(256, 1) void hgemm_qkv(
    const float* __restrict__ b_q, const float* __restrict__ b_k,
    const float* __restrict__ b_v)
{
    extern __shared__ __nv_bfloat16 smg[];
    const int z = blockIdx.z;
    if (z == 0)
        hgemm_body(g_A0hi, g_A0lo, g_W0hi, g_W0lo, b_q, nullptr, g_Qhi, g_Qlo, 1, smg);
    else if (z == 1)
        hgemm_body(g_A1hi, g_A1lo, g_W1hi, g_W1lo, b_k, nullptr, g_Khi, g_Klo, 1, smg);
    else
        hgemm_body(g_A2hi, g_A2lo, g_W2hi, g_W2lo, b_v, nullptr, g_Vthi, g_Vtlo, 2, smg);
}

__global__ __launch_bounds__(256, 1) void hgemm_out(
    const float* __restrict__ b_o, float* __restrict__ out)
{
    extern __shared__ __nv_bfloat16 smg[];
    hgemm_body(g_Xhi, g_Xlo, g_W3hi, g_W3lo, b_o, out, nullptr, nullptr, 0, smg);
}

// ---------------------------------------------------------------------------
// HMMA flash attention, bf16x3, causal, cp.async double-buffered KV.
// CTA: 64 query rows of one (b,h); 4 warps x 16 rows. KV tiles of 64 keys.
// ---------------------------------------------------------------------------
#define APAD 72
#define A_TILE (64 * APAD)             // 4608 halves = 9216 B
#define STAGE_H (4 * A_TILE)           // KH,KL,VH,VL per stage
#define ATTN_SMEM ((2 * A_TILE + 2 * STAGE_H) * 2)   // 92160 B

__global__ __launch_bounds__(128, 1) void attn_mma_kernel(
    const __nv_bfloat16* __restrict__ Qhi, const __nv_bfloat16* __restrict__ Qlo,
    const __nv_bfloat16* __restrict__ Khi, const __nv_bfloat16* __restrict__ Klo,
    const __nv_bfloat16* __restrict__ Vthi, const __nv_bfloat16* __restrict__ Vtlo,
    __nv_bfloat16* __restrict__ Xhi, __nv_bfloat16* __restrict__ Xlo)
{
    extern __shared__ __nv_bfloat16 smA[];
    const int tid  = threadIdx.x;
    const int w    = tid >> 5, lane = tid & 31;
    const int bh   = blockIdx.y;
    const int iq   = gridDim.x - 1 - blockIdx.x;   // long CTAs first
    const size_t baseQK = (size_t)bh * Ss * DKk;
    const size_t baseV  = (size_t)bh * DKk * Ss;
    const uint32_t sb = smem_u32(smA);

    #define ISSUE_KV(j, stg) do {                                               \
        const __nv_bfloat16* Kh_g = Khi + baseQK + (size_t)(j) * 64 * DKk;      \
        const __nv_bfloat16* Kl_g = Klo + baseQK + (size_t)(j) * 64 * DKk;      \
        const __nv_bfloat16* Vh_g = Vthi + baseV + (size_t)(j) * 64;            \
        const __nv_bfloat16* Vl_g = Vtlo + baseV + (size_t)(j) * 64;            \
        const uint32_t st = sb + (uint32_t)((2 * A_TILE + (stg) * STAGE_H) * 2);\
        _Pragma("unroll")                                                       \
        for (int t = 0; t < 4; t++) {                                           \
            int idx = tid + t * 128;                                            \
            int row = idx >> 3, cu = (idx & 7) * 8;                             \
            cpasync16(st + (uint32_t)((0 * A_TILE + row * APAD + cu) * 2),      \
                      &Kh_g[row * DKk + cu]);                                   \
            cpasync16(st + (uint32_t)((1 * A_TILE + row * APAD + cu) * 2),      \
                      &Kl_g[row * DKk + cu]);                                   \
            cpasync16(st + (uint32_t)((2 * A_TILE + row * APAD + cu) * 2),      \
                      &Vh_g[(size_t)row * Ss + cu]);                            \
            cpasync16(st + (uint32_t)((3 * A_TILE + row * APAD + cu) * 2),      \
                      &Vl_g[(size_t)row * Ss + cu]);                            \
        }                                                                       \
        CP_COMMIT();                                                            \
    } while (0)

    // ---- load Q tile (64x64 hi/lo) + prefetch KV tile 0 ----
    {
        const __nv_bfloat16* Qh_g = Qhi + baseQK + (size_t)iq * 64 * DKk;
        const __nv_bfloat16* Ql_g = Qlo + baseQK + (size_t)iq * 64 * DKk;
        #pragma unroll
        for (int t = 0; t < 4; t++) {
            int idx = tid + t * 128;
            int row = idx >> 3, cu = (idx & 7) * 8;
            *(uint4*)&smA[0 * A_TILE + row * APAD + cu] = *(const uint4*)&Qh_g[row * DKk + cu];
            *(uint4*)&smA[1 * A_TILE + row * APAD + cu] = *(const uint4*)&Ql_g[row * DKk + cu];
        }
    }
    ISSUE_KV(0, 0);
    __syncthreads();

    const uint32_t a_off = (uint32_t)(((w * 16 + (lane & 15)) * APAD + (lane >> 4) * 8) * 2);
    const uint32_t b_off = (uint32_t)((((lane & 15)) * APAD + (lane >> 4) * 8) * 2);

    uint32_t qh[4][4], ql[4][4];
    #pragma unroll
    for (int kk = 0; kk < 4; kk++) {
        ldsm4(sb + 0 * A_TILE * 2 + a_off + kk * 32, qh[kk][0], qh[kk][1], qh[kk][2], qh[kk][3]);
        ldsm4(sb + 1 * A_TILE * 2 + a_off + kk * 32, ql[kk][0], ql[kk][1], ql[kk][2], ql[kk][3]);
    }

    float o[8][4];
    #pragma unroll
    for (int i = 0; i < 8; i++)
        #pragma unroll
        for (int r = 0; r < 4; r++) o[i][r] = 0.f;
    float m_lo = -1e30f, m_hi = -1e30f, l_lo = 0.f, l_hi = 0.f;

    for (int j = 0; j <= iq; j++) {
        CP_WAIT0();
        __syncthreads();
        if (j < iq) ISSUE_KV(j + 1, (j + 1) & 1);

        const uint32_t stb = sb + (uint32_t)((2 * A_TILE + (j & 1) * STAGE_H) * 2);

        // ---- scores S = Q K^T (3-term) ----
        float s[8][4];
        #pragma unroll
        for (int i = 0; i < 8; i++)
            #pragma unroll
            for (int r = 0; r < 4; r++) s[i][r] = 0.f;

        #pragma unroll
        for (int kk = 0; kk < 4; kk++) {
            uint32_t kh[8][2], kl[8][2];
            #pragma unroll
            for (int np = 0; np < 4; np++) {
                uint32_t t0, t1, t2, t3;
                ldsm4(stb + 0 * A_TILE * 2 + b_off + np * (16 * APAD * 2) + kk * 32, t0, t1, t2, t3);
                kh[2 * np][0] = t0; kh[2 * np][1] = t2;
                kh[2 * np + 1][0] = t1; kh[2 * np + 1][1] = t3;
                ldsm4(stb + 1 * A_TILE * 2 + b_off + np * (16 * APAD * 2) + kk * 32, t0, t1, t2, t3);
                kl[2 * np][0] = t0; kl[2 * np][1] = t2;
                kl[2 * np + 1][0] = t1; kl[2 * np + 1][1] = t3;
            }
            #pragma unroll
            for (int ni = 0; ni < 8; ni++)
                mma16816(s[ni], qh[kk][0], qh[kk][1], qh[kk][2], qh[kk][3],
                         kh[ni][0], kh[ni][1]);
            #pragma unroll
            for (int ni = 0; ni < 8; ni++)
                mma16816(s[ni], qh[kk][0], qh[kk][1], qh[kk][2], qh[kk][3],
                         kl[ni][0], kl[ni][1]);
            #pragma unroll
            for (int ni = 0; ni < 8; ni++)
                mma16816(s[ni], ql[kk][0], ql[kk][1], ql[kk][2], ql[kk][3],
                         kh[ni][0], kh[ni][1]);
        }

        // ---- scale + causal mask (diagonal tile only) ----
        #pragma unroll
        for (int ni = 0; ni < 8; ni++)
            #pragma unroll
            for (int r = 0; r < 4; r++) s[ni][r] *= 0.125f;
        if (j == iq) {
            const int rlo = w * 16 + (lane >> 2), rhi = rlo + 8;
            #pragma unroll
            for (int ni = 0; ni < 8; ni++) {
                const int c0 = ni * 8 + (lane & 3) * 2;
                if (c0 > rlo)     s[ni][0] = -1e30f;
                if (c0 + 1 > rlo) s[ni][1] = -1e30f;
                if (c0 > rhi)     s[ni][2] = -1e30f;
                if (c0 + 1 > rhi) s[ni][3] = -1e30f;
            }
        }

        // ---- online softmax (fp32) ----
        float mx_lo = s[0][0], mx_hi = s[0][2];
        #pragma unroll
        for (int ni = 0; ni < 8; ni++) {
            mx_lo = fmaxf(mx_lo, fmaxf(s[ni][0], s[ni][1]));
            mx_hi = fmaxf(mx_hi, fmaxf(s[ni][2], s[ni][3]));
        }
        mx_lo = fmaxf(mx_lo, __shfl_xor_sync(0xffffffffu, mx_lo, 1));
        mx_lo = fmaxf(mx_lo, __shfl_xor_sync(0xffffffffu, mx_lo, 2));
        mx_hi = fmaxf(mx_hi, __shfl_xor_sync(0xffffffffu, mx_hi, 1));
        mx_hi = fmaxf(mx_hi, __shfl_xor_sync(0xffffffffu, mx_hi, 2));
        const float mn_lo = fmaxf(m_lo, mx_lo), mn_hi = fmaxf(m_hi, mx_hi);
        const float al_lo = __expf(m_lo - mn_lo), al_hi = __expf(m_hi - mn_hi);

        uint32_t ph[8][2], pl[8][2];
        float sum_lo = 0.f, sum_hi = 0.f;
        #pragma unroll
        for (int ni = 0; ni < 8; ni++) {
            float p0 = __expf(s[ni][0] - mn_lo);
            float p1 = __expf(s[ni][1] - mn_lo);
            float p2 = __expf(s[ni][2] - mn_hi);
            float p3 = __expf(s[ni][3] - mn_hi);
            sum_lo += p0 + p1; sum_hi += p2 + p3;
            uint32_t h01 = packbf(p0, p1), h23 = packbf(p2, p3);
            ph[ni][0] = h01; ph[ni][1] = h23;
            pl[ni][0] = packbf(p0 - bflo_f(h01), p1 - bfhi_f(h01));
            pl[ni][1] = packbf(p2 - bflo_f(h23), p3 - bfhi_f(h23));
        }
        sum_lo += __shfl_xor_sync(0xffffffffu, sum_lo, 1);
        sum_lo += __shfl_xor_sync(0xffffffffu, sum_lo, 2);
        sum_hi += __shfl_xor_sync(0xffffffffu, sum_hi, 1);
        sum_hi += __shfl_xor_sync(0xffffffffu, sum_hi, 2);
        l_lo = l_lo * al_lo + sum_lo;  m_lo = mn_lo;
        l_hi = l_hi * al_hi + sum_hi;  m_hi = mn_hi;
        #pragma unroll
        for (int ni = 0; ni < 8; ni++) {
            o[ni][0] *= al_lo; o[ni][1] *= al_lo;
            o[ni][2] *= al_hi; o[ni][3] *= al_hi;
        }

        // ---- O += P V (3-term) ----
        #pragma unroll
        for (int kk = 0; kk < 4; kk++) {
            uint32_t vh[8][2], vl[8][2];
            #pragma unroll
            for (int np = 0; np < 4; np++) {
                uint32_t t0, t1, t2, t3;
                ldsm4(stb + 2 * A_TILE * 2 + b_off + np * (16 * APAD * 2) + kk * 32, t0, t1, t2, t3);
                vh[2 * np][0] = t0; vh[2 * np][1] = t2;
                vh[2 * np + 1][0] = t1; vh[2 * np + 1][1] = t3;
                ldsm4(stb + 3 * A_TILE * 2 + b_off + np * (16 * APAD * 2) + kk * 32, t0, t1, t2, t3);
                vl[2 * np][0] = t0; vl[2 * np][1] = t2;
                vl[2 * np + 1][0] = t1; vl[2 * np + 1][1] = t3;
            }
            const uint32_t pa0 = ph[2 * kk][0], pa1 = ph[2 * kk][1];
            const uint32_t pa2 = ph[2 * kk + 1][0], pa3 = ph[2 * kk + 1][1];
            const uint32_t qa0 = pl[2 * kk][0], qa1 = pl[2 * kk][1];
            const uint32_t qa2 = pl[2 * kk + 1][0], qa3 = pl[2 * kk + 1][1];
            #pragma unroll
            for (int ni = 0; ni < 8; ni++)
                mma16816(o[ni], pa0, pa1, pa2, pa3, vh[ni][0], vh[ni][1]);
            #pragma unroll
            for (int ni = 0; ni < 8; ni++)
                mma16816(o[ni], pa0, pa1, pa2, pa3, vl[ni][0], vl[ni][1]);
            #pragma unroll
            for (int ni = 0; ni < 8; ni++)
                mma16816(o[ni], qa0, qa1, qa2, qa3, vh[ni][0], vh[ni][1]);
        }
    }

    // ---- epilogue: X[b, s, h*64+dk] as bf16 hi/lo ----
    const float inv_lo = 1.f / l_lo, inv_hi = 1.f / l_hi;
    const int b = bh >> 4, h = bh & 15;
    const int s_lo = iq * 64 + w * 16 + (lane >> 2);
    const int s_hi = s_lo + 8;
    #pragma unroll
    for (int ni = 0; ni < 8; ni++) {
        const int dk = ni * 8 + (lane & 3) * 2;
        const size_t o_lo = ((size_t)(b * Ss + s_lo)) * Dd + h * DKk + dk;
        const size_t o_hi = ((size_t)(b * Ss + s_hi)) * Dd + h * DKk + dk;
        float v0 = o[ni][0] * inv_lo, v1 = o[ni][1] * inv_lo;
        float v2 = o[ni][2] * inv_hi, v3 = o[ni][3] * inv_hi;
        uint32_t hp0 = packbf(v0, v1), hp1 = packbf(v2, v3);
        *(uint32_t*)&Xhi[o_lo] = hp0;
        *(uint32_t*)&Xhi[o_hi] = hp1;
        *(uint32_t*)&Xlo[o_lo] = packbf(v0 - bflo_f(hp0), v1 - bfhi_f(hp0));
        *(uint32_t*)&Xlo[o_hi] = packbf(v2 - bflo_f(hp1), v3 - bfhi_f(hp1));
    }
    #undef ISSUE_KV
}

// ---------------------------------------------------------------------------
extern "C" void kernel_launch(void* const* d_in, const int* in_sizes, int n_in,
                              void* d_out, int out_size)
{
    const float* q   = (const float*)d_in[0];
    const float* k   = (const float*)d_in[1];
    const float* v   = (const float*)d_in[2];
    // d_in[3] = causal mask (int32) — causality computed analytically
    const float* w_q = (const float*)d_in[4];
    const float* b_q = (const float*)d_in[5];
    const float* w_k = (const float*)d_in[6];
    const float* b_k = (const float*)d_in[7];
    const float* w_v = (const float*)d_in[8];
    const float* b_v = (const float*)d_in[9];
    const float* w_o = (const float*)d_in[10];
    const float* b_o = (const float*)d_in[11];
    float* out = (float*)d_out;

    __nv_bfloat16 *pQh, *pQl, *pKh, *pKl, *pVh, *pVl, *pXh, *pXl;
    cudaGetSymbolAddress((void**)&pQh, g_Qhi);
    cudaGetSymbolAddress((void**)&pQl, g_Qlo);
    cudaGetSymbolAddress((void**)&pKh, g_Khi);
    cudaGetSymbolAddress((void**)&pKl, g_Klo);
    cudaGetSymbolAddress((void**)&pVh, g_Vthi);
    cudaGetSymbolAddress((void**)&pVl, g_Vtlo);
    cudaGetSymbolAddress((void**)&pXh, g_Xhi);
    cudaGetSymbolAddress((void**)&pXl, g_Xlo);

    cudaFuncSetAttribute(hgemm_qkv,
                         cudaFuncAttributeMaxDynamicSharedMemorySize, GSMEM);
    cudaFuncSetAttribute(hgemm_out,
                         cudaFuncAttributeMaxDynamicSharedMemorySize, GSMEM);
    cudaFuncSetAttribute(attn_mma_kernel,
                         cudaFuncAttributeMaxDynamicSharedMemorySize, ATTN_SMEM);

    // conversions (weights + activations)
    dim3 wt_grid(32, 32, 4), wt_block(32, 8);
    conv_wt_all<<<wt_grid, wt_block>>>(w_q, w_k, w_v, w_o);
    dim3 ca_grid(4096, 3);
    conv_act_all<<<ca_grid, 256>>>(q, k, v);

    // batched QKV projections
    dim3 gemm_grid(Dd / 128, Mm / 128, 3);             // (8, 32, 3)
    hgemm_qkv<<<gemm_grid, 256, GSMEM>>>(b_q, b_k, b_v);

    // attention
    dim3 agrid(Ss / 64, Bb * Hh);                      // (32, 32)
    attn_mma_kernel<<<agrid, 128, ATTN_SMEM>>>(pQh, pQl, pKh, pKl, pVh, pVl, pXh, pXl);

    // output projection
    dim3 gemm_grid1(Dd / 128, Mm / 128, 1);
    hgemm_out<<<gemm_grid1, 256, GSMEM>>>(b_o, out);
}

// round 8
// speedup vs baseline: 3.4275x; 1.1105x over previous
#include <cuda_runtime.h>
#include <cuda_bf16.h>
#include <cstdint>

#define Bb  2
#define Ss  2048
#define Dd  1024
#define Hh  16
#define DKk 64
#define Mm  (Bb*Ss)

// ---------------- scratch (allocation-free: device globals) ----------------
__device__ __nv_bfloat16 g_A0hi[(size_t)Mm*Dd], g_A0lo[(size_t)Mm*Dd];
__device__ __nv_bfloat16 g_A1hi[(size_t)Mm*Dd], g_A1lo[(size_t)Mm*Dd];
__device__ __nv_bfloat16 g_A2hi[(size_t)Mm*Dd], g_A2lo[(size_t)Mm*Dd];
__device__ __nv_bfloat16 g_W0hi[(size_t)Dd*Dd], g_W0lo[(size_t)Dd*Dd];
__device__ __nv_bfloat16 g_W1hi[(size_t)Dd*Dd], g_W1lo[(size_t)Dd*Dd];
__device__ __nv_bfloat16 g_W2hi[(size_t)Dd*Dd], g_W2lo[(size_t)Dd*Dd];
__device__ __nv_bfloat16 g_W3hi[(size_t)Dd*Dd], g_W3lo[(size_t)Dd*Dd];
__device__ __nv_bfloat16 g_Qhi[(size_t)Bb*Hh*Ss*DKk], g_Qlo[(size_t)Bb*Hh*Ss*DKk];
__device__ __nv_bfloat16 g_Khi[(size_t)Bb*Hh*Ss*DKk], g_Klo[(size_t)Bb*Hh*Ss*DKk];
__device__ __nv_bfloat16 g_Vthi[(size_t)Bb*Hh*DKk*Ss], g_Vtlo[(size_t)Bb*Hh*DKk*Ss];
__device__ __nv_bfloat16 g_Xhi[(size_t)Mm*Dd], g_Xlo[(size_t)Mm*Dd];

// ---------------- helpers (arch-portable PTX) --------
__device__ __forceinline__ uint32_t smem_u32(const void* p) {
    uint32_t a;
    asm("{ .reg .u64 t; cvta.to.shared.u64 t, %1; cvt.u32.u64 %0, t; }"
        : "=r"(a) : "l"(p));
    return a;
}
__device__ __forceinline__ void ldsm4(uint32_t a, uint32_t& r0, uint32_t& r1,
                                      uint32_t& r2, uint32_t& r3) {
    asm volatile("ldmatrix.sync.aligned.m8n8.x4.shared.b16 {%0,%1,%2,%3}, [%4];"
                 : "=r"(r0), "=r"(r1), "=r"(r2), "=r"(r3) : "r"(a));
}
__device__ __forceinline__ void mma16816(float* c, uint32_t a0, uint32_t a1,
                                         uint32_t a2, uint32_t a3,
                                         uint32_t b0, uint32_t b1) {
    asm volatile(
        "mma.sync.aligned.m16n8k16.row.col.f32.bf16.bf16.f32 "
        "{%0,%1,%2,%3}, {%4,%5,%6,%7}, {%8,%9}, {%0,%1,%2,%3};"
        : "+f"(c[0]), "+f"(c[1]), "+f"(c[2]), "+f"(c[3])
        : "r"(a0), "r"(a1), "r"(a2), "r"(a3), "r"(b0), "r"(b1));
}
__device__ __forceinline__ uint32_t packbf(float lo, float hi) {
    uint32_t r;
    asm("cvt.rn.bf16x2.f32 %0, %1, %2;" : "=r"(r) : "f"(hi), "f"(lo));
    return r;
}
__device__ __forceinline__ float bflo_f(uint32_t p) { return __uint_as_float(p << 16); }
__device__ __forceinline__ float bfhi_f(uint32_t p) { return __uint_as_float(p & 0xffff0000u); }
__device__ __forceinline__ float ex2f(float x) {
    float r;
    asm("ex2.approx.f32 %0, %1;" : "=f"(r) : "f"(x));
    return r;
}

__device__ __forceinline__ void cpasync16(uint32_t saddr, const void* g) {
    asm volatile("cp.async.ca.shared.global [%0], [%1], 16;"
                 :: "r"(saddr), "l"(g) : "memory");
}
#define CP_COMMIT() asm volatile("cp.async.commit_group;" ::: "memory")
#define CP_WAIT0()  asm volatile("cp.async.wait_group 0;" ::: "memory")

// ---------------------------------------------------------------------------
// merged fp32 -> bf16 hi/lo splits for q,k,v activations
// ---------------------------------------------------------------------------
__global__ __launch_bounds__(256) void conv_act_all(
    const float* __restrict__ q, const float* __restrict__ k,
    const float* __restrict__ v)
{
    const float* src = (blockIdx.y == 0) ? q : (blockIdx.y == 1) ? k : v;
    __nv_bfloat16* hi = (blockIdx.y == 0) ? g_A0hi : (blockIdx.y == 1) ? g_A1hi : g_A2hi;
    __nv_bfloat16* lo = (blockIdx.y == 0) ? g_A0lo : (blockIdx.y == 1) ? g_A1lo : g_A2lo;
    int i = blockIdx.x * blockDim.x + threadIdx.x;
    float4 vv = ((const float4*)src)[i];
    uint32_t h0 = packbf(vv.x, vv.y), h1 = packbf(vv.z, vv.w);
    ((uint32_t*)hi)[i * 2 + 0] = h0;
    ((uint32_t*)hi)[i * 2 + 1] = h1;
    ((uint32_t*)lo)[i * 2 + 0] = packbf(vv.x - bflo_f(h0), vv.y - bfhi_f(h0));
    ((uint32_t*)lo)[i * 2 + 1] = packbf(vv.z - bflo_f(h1), vv.w - bfhi_f(h1));
}

// ---------------------------------------------------------------------------
// merged weight transpose + split: W[K,N] -> WT[N,K] hi/lo, 4 weights
// ---------------------------------------------------------------------------
__global__ __launch_bounds__(256) void conv_wt_all(
    const float* __restrict__ w0, const float* __restrict__ w1,
    const float* __restrict__ w2, const float* __restrict__ w3)
{
    __shared__ float ts[32][33];
    const int z = blockIdx.z;
    const float* W = (z == 0) ? w0 : (z == 1) ? w1 : (z == 2) ? w2 : w3;
    __nv_bfloat16* hiT = (z == 0) ? g_W0hi : (z == 1) ? g_W1hi : (z == 2) ? g_W2hi : g_W3hi;
    __nv_bfloat16* loT = (z == 0) ? g_W0lo : (z == 1) ? g_W1lo : (z == 2) ? g_W2lo : g_W3lo;
    int tx = threadIdx.x, ty = threadIdx.y;          // 32 x 8
    int bn = blockIdx.x * 32, bk = blockIdx.y * 32;
    #pragma unroll
    for (int r = 0; r < 4; r++)
        ts[ty + r * 8][tx] = W[(size_t)(bk + ty + r * 8) * Dd + bn + tx];
    __syncthreads();
    #pragma unroll
    for (int r = 0; r < 4; r++) {
        float x = ts[tx][ty + r * 8];
        __nv_bfloat16 h = __float2bfloat16(x);
        size_t o = (size_t)(bn + ty + r * 8) * Dd + bk + tx;
        hiT[o] = h;
        loT[o] = __float2bfloat16(x - __bfloat162float(h));
    }
}

// ---------------------------------------------------------------------------
// HMMA bf16x3 GEMM body: cp.async double-buffered, 2 CTAs/SM.
// CTA 128x128, K-chunk 32, 8 warps (2m x 4n), warp tile 64x32.
// mode 0: fp32 row-major; 1: bf16 hi/lo [B,H,S,DK]; 2: bf16 hi/lo [B,H,DK,S].
// ---------------------------------------------------------------------------
#define KCH   32
#define NCHUNK (Dd / KCH)          // 32
#define SROW  40                   // padded halves per row
#define ABYTES (128 * SROW * 2)    // 10240 B per array
#define BUFB  (4 * ABYTES)         // 40960 B per stage
#define GSMEM (2 * BUFB)           // 81920 B

__device__ __forceinline__ void hgemm_body(
    const __nv_bfloat16* __restrict__ Ahi, const __nv_bfloat16* __restrict__ Alo,
    const __nv_bfloat16* __restrict__ Whi, const __nv_bfloat16* __restrict__ Wlo,
    const float* __restrict__ bias, float* __restrict__ Cf,
    __nv_bfloat16* __restrict__ Chi, __nv_bfloat16* __restrict__ Clo,
    int mode, __nv_bfloat16* sm)
{
    const int tid  = threadIdx.x;
    const int wid  = tid >> 5, lane = tid & 31;
    const int bm   = blockIdx.y * 128, bn = blockIdx.x * 128;
    const int wm   = wid & 1, wn = wid >> 1;

    float c[4][4][4];
    #pragma unroll
    for (int i = 0; i < 4; i++)
        #pragma unroll
        for (int j = 0; j < 4; j++)
            #pragma unroll
            for (int r = 0; r < 4; r++) c[i][j][r] = 0.f;

    const int r0 = tid >> 2,         q0 = (tid & 3) * 8;
    const int r1 = (tid + 256) >> 2, q1 = ((tid + 256) & 3) * 8;
    const uint32_t sb = smem_u32(sm);

    #define ISSUE_CHUNK(cc, base) do {                                          \
        const int k0_ = (cc) * KCH;                                             \
        cpasync16((base) + (uint32_t)((0 * 128 * SROW + r0 * SROW + q0) * 2),   \
                  &Ahi[(size_t)(bm + r0) * Dd + k0_ + q0]);                     \
        cpasync16((base) + (uint32_t)((0 * 128 * SROW + r1 * SROW + q1) * 2),   \
                  &Ahi[(size_t)(bm + r1) * Dd + k0_ + q1]);                     \
        cpasync16((base) + (uint32_t)((1 * 128 * SROW + r0 * SROW + q0) * 2),   \
                  &Alo[(size_t)(bm + r0) * Dd + k0_ + q0]);                     \
        cpasync16((base) + (uint32_t)((1 * 128 * SROW + r1 * SROW + q1) * 2),   \
                  &Alo[(size_t)(bm + r1) * Dd + k0_ + q1]);                     \
        cpasync16((base) + (uint32_t)((2 * 128 * SROW + r0 * SROW + q0) * 2),   \
                  &Whi[(size_t)(bn + r0) * Dd + k0_ + q0]);                     \
        cpasync16((base) + (uint32_t)((2 * 128 * SROW + r1 * SROW + q1) * 2),   \
                  &Whi[(size_t)(bn + r1) * Dd + k0_ + q1]);                     \
        cpasync16((base) + (uint32_t)((3 * 128 * SROW + r0 * SROW + q0) * 2),   \
                  &Wlo[(size_t)(bn + r0) * Dd + k0_ + q0]);                     \
        cpasync16((base) + (uint32_t)((3 * 128 * SROW + r1 * SROW + q1) * 2),   \
                  &Wlo[(size_t)(bn + r1) * Dd + k0_ + q1]);                     \
        CP_COMMIT();                                                            \
    } while (0)

    const uint32_t aoff =
        (uint32_t)(((wm * 64 + (lane & 15)) * SROW + (lane >> 4) * 8) * 2);
    // B ldsm4: lanes 0-7 -> (n0,k0), 8-15 -> (n0,k8), 16-23 -> (n1,k0), 24-31 -> (n1,k8)
    const uint32_t boff4 =
        (uint32_t)(((wn * 32 + (lane >> 4) * 8 + (lane & 7)) * SROW
                    + ((lane >> 3) & 1) * 8) * 2);

    ISSUE_CHUNK(0, sb);

    for (int cc = 0; cc < NCHUNK; cc++) {
        CP_WAIT0();
        __syncthreads();
        if (cc + 1 < NCHUNK)
            ISSUE_CHUNK(cc + 1, sb + (uint32_t)((cc + 1) & 1) * BUFB);

        const uint32_t bufb = sb + (uint32_t)(cc & 1) * BUFB;
        #pragma unroll
        for (int pass = 0; pass < 3; pass++) {
            const uint32_t Ab  = bufb + aoff + (pass == 2 ? (uint32_t)ABYTES : 0u);
            const uint32_t Bbp = bufb + boff4 + 2u * ABYTES + (pass == 1 ? (uint32_t)ABYTES : 0u);
            #pragma unroll
            for (int ks = 0; ks < 2; ks++) {
                uint32_t a[4][4], b[4][2];
                #pragma unroll
                for (int mi = 0; mi < 4; mi++)
                    ldsm4(Ab + mi * (16 * SROW * 2) + ks * 32,
                          a[mi][0], a[mi][1], a[mi][2], a[mi][3]);
                #pragma unroll
                for (int nb = 0; nb < 2; nb++)
                    ldsm4(Bbp + nb * (16 * SROW * 2) + ks * 32,
                          b[2 * nb][0], b[2 * nb][1], b[2 * nb + 1][0], b[2 * nb + 1][1]);
                #pragma unroll
                for (int mi = 0; mi < 4; mi++)
                    #pragma unroll
                    for (int ni = 0; ni < 4; ni++)
                        mma16816(c[mi][ni], a[mi][0], a[mi][1], a[mi][2], a[mi][3],
                                 b[ni][0], b[ni][1]);
            }
        }
    }

    // ---- epilogue ----
    const int mrow0 = bm + wm * 64 + (lane >> 2);
    const int ncol0 = bn + wn * 32 + (lane & 3) * 2;
    #pragma unroll
    for (int mi = 0; mi < 4; mi++) {
        #pragma unroll
        for (int h2 = 0; h2 < 2; h2++) {
            const int m = mrow0 + mi * 16 + h2 * 8;
            const int b = m >> 11, s = m & 2047;
            #pragma unroll
            for (int ni = 0; ni < 4; ni++) {
                const int n = ncol0 + ni * 8;
                float v0 = c[mi][ni][h2 * 2 + 0] + bias[n];
                float v1 = c[mi][ni][h2 * 2 + 1] + bias[n + 1];
                if (mode == 0) {
                    float2 v; v.x = v0; v.y = v1;
                    *(float2*)&Cf[(size_t)m * Dd + n] = v;
                } else {
                    const int h = n >> 6, dk = n & 63;
                    uint32_t hp = packbf(v0, v1);
                    uint32_t lp = packbf(v0 - bflo_f(hp), v1 - bfhi_f(hp));
                    if (mode == 1) {
                        size_t o = (((size_t)(b * Hh + h)) * Ss + s) * DKk + dk;
                        *(uint32_t*)&Chi[o] = hp;
                        *(uint32_t*)&Clo[o] = lp;
                    } else {
                        size_t o = (((size_t)(b * Hh + h)) * DKk + dk) * Ss + s;
                        Chi[o]      = __ushort_as_bfloat16((uint16_t)(hp & 0xffff));
                        Chi[o + Ss] = __ushort_as_bfloat16((uint16_t)(hp >> 16));
                        Clo[o]      = __ushort_as_bfloat16((uint16_t)(lp & 0xffff));
                        Clo[o + Ss] = __ushort_as_bfloat16((uint16_t)(lp >> 16));
                    }
                }
            }
        }
    }
    #undef ISSUE_CHUNK
}

// batched QKV projections: blockIdx.z selects {Q, K, V}
__global__ __launch_bounds__(256, 2) void hgemm_qkv(
    const float* __restrict__ b_q, const float* __restrict__ b_k,
    const float* __restrict__ b_v)
{
    extern __shared__ __nv_bfloat16 smg[];
    const int z = blockIdx.z;
    if (z == 0)
        hgemm_body(g_A0hi, g_A0lo, g_W0hi, g_W0lo, b_q, nullptr, g_Qhi, g_Qlo, 1, smg);
    else if (z == 1)
        hgemm_body(g_A1hi, g_A1lo, g_W1hi, g_W1lo, b_k, nullptr, g_Khi, g_Klo, 1, smg);
    else
        hgemm_body(g_A2hi, g_A2lo, g_W2hi, g_W2lo, b_v, nullptr, g_Vthi, g_Vtlo, 2, smg);
}

__global__ __launch_bounds__(256, 2) void hgemm_out(
    const float* __restrict__ b_o, float* __restrict__ out)
{
    extern __shared__ __nv_bfloat16 smg[];
    hgemm_body(g_Xhi, g_Xlo, g_W3hi, g_W3lo, b_o, out, nullptr, nullptr, 0, smg);
}

// ---------------------------------------------------------------------------
// HMMA flash attention, bf16x3, causal, cp.async double-buffered KV.
// CTA: 64 query rows of one (b,h); 4 warps x 16 rows. KV tiles of 64 keys.
// ---------------------------------------------------------------------------
#define APAD 72
#define A_TILE (64 * APAD)             // 4608 halves = 9216 B
#define STAGE_H (4 * A_TILE)           // KH,KL,VH,VL per stage
#define ATTN_SMEM ((2 * A_TILE + 2 * STAGE_H) * 2)   // 92160 B
#define SCL2 0.18033688f               // 0.125 * log2(e)

__global__ __launch_bounds__(128, 1) void attn_mma_kernel(
    const __nv_bfloat16* __restrict__ Qhi, const __nv_bfloat16* __restrict__ Qlo,
    const __nv_bfloat16* __restrict__ Khi, const __nv_bfloat16* __restrict__ Klo,
    const __nv_bfloat16* __restrict__ Vthi, const __nv_bfloat16* __restrict__ Vtlo,
    __nv_bfloat16* __restrict__ Xhi, __nv_bfloat16* __restrict__ Xlo)
{
    extern __shared__ __nv_bfloat16 smA[];
    const int tid  = threadIdx.x;
    const int w    = tid >> 5, lane = tid & 31;
    const int bh   = blockIdx.y;
    const int iq   = gridDim.x - 1 - blockIdx.x;   // long CTAs first
    const size_t baseQK = (size_t)bh * Ss * DKk;
    const size_t baseV  = (size_t)bh * DKk * Ss;
    const uint32_t sb = smem_u32(smA);

    #define ISSUE_KV(j, stg) do {                                               \
        const __nv_bfloat16* Kh_g = Khi + baseQK + (size_t)(j) * 64 * DKk;      \
        const __nv_bfloat16* Kl_g = Klo + baseQK + (size_t)(j) * 64 * DKk;      \
        const __nv_bfloat16* Vh_g = Vthi + baseV + (size_t)(j) * 64;            \
        const __nv_bfloat16* Vl_g = Vtlo + baseV + (size_t)(j) * 64;            \
        const uint32_t st = sb + (uint32_t)((2 * A_TILE + (stg) * STAGE_H) * 2);\
        _Pragma("unroll")                                                       \
        for (int t = 0; t < 4; t++) {                                           \
            int idx = tid + t * 128;                                            \
            int row = idx >> 3, cu = (idx & 7) * 8;                             \
            cpasync16(st + (uint32_t)((0 * A_TILE + row * APAD + cu) * 2),      \
                      &Kh_g[row * DKk + cu]);                                   \
            cpasync16(st + (uint32_t)((1 * A_TILE + row * APAD + cu) * 2),      \
                      &Kl_g[row * DKk + cu]);                                   \
            cpasync16(st + (uint32_t)((2 * A_TILE + row * APAD + cu) * 2),      \
                      &Vh_g[(size_t)row * Ss + cu]);                            \
            cpasync16(st + (uint32_t)((3 * A_TILE + row * APAD + cu) * 2),      \
                      &Vl_g[(size_t)row * Ss + cu]);                            \
        }                                                                       \
        CP_COMMIT();                                                            \
    } while (0)

    // ---- load Q tile (64x64 hi/lo) + prefetch KV tile 0 ----
    {
        const __nv_bfloat16* Qh_g = Qhi + baseQK + (size_t)iq * 64 * DKk;
        const __nv_bfloat16* Ql_g = Qlo + baseQK + (size_t)iq * 64 * DKk;
        #pragma unroll
        for (int t = 0; t < 4; t++) {
            int idx = tid + t * 128;
            int row = idx >> 3, cu = (idx & 7) * 8;
            *(uint4*)&smA[0 * A_TILE + row * APAD + cu] = *(const uint4*)&Qh_g[row * DKk + cu];
            *(uint4*)&smA[1 * A_TILE + row * APAD + cu] = *(const uint4*)&Ql_g[row * DKk + cu];
        }
    }
    ISSUE_KV(0, 0);
    __syncthreads();

    const uint32_t a_off = (uint32_t)(((w * 16 + (lane & 15)) * APAD + (lane >> 4) * 8) * 2);
    const uint32_t b_off = (uint32_t)((((lane & 15)) * APAD + (lane >> 4) * 8) * 2);

    uint32_t qh[4][4], ql[4][4];
    #pragma unroll
    for (int kk = 0; kk < 4; kk++) {
        ldsm4(sb + 0 * A_TILE * 2 + a_off + kk * 32, qh[kk][0], qh[kk][1], qh[kk][2], qh[kk][3]);
        ldsm4(sb + 1 * A_TILE * 2 + a_off + kk * 32, ql[kk][0], ql[kk][1], ql[kk][2], ql[kk][3]);
    }

    float o[8][4];
    #pragma unroll
    for (int i = 0; i < 8; i++)
        #pragma unroll
        for (int r = 0; r < 4; r++) o[i][r] = 0.f;
    float m_lo = -1e30f, m_hi = -1e30f, l_lo = 0.f, l_hi = 0.f;

    for (int j = 0; j <= iq; j++) {
        CP_WAIT0();
        __syncthreads();
        if (j < iq) ISSUE_KV(j + 1, (j + 1) & 1);

        const uint32_t stb = sb + (uint32_t)((2 * A_TILE + (j & 1) * STAGE_H) * 2);

        // ---- scores S = Q K^T (3-term) ----
        float s[8][4];
        #pragma unroll
        for (int i = 0; i < 8; i++)
            #pragma unroll
            for (int r = 0; r < 4; r++) s[i][r] = 0.f;

        #pragma unroll
        for (int kk = 0; kk < 4; kk++) {
            uint32_t kh[8][2], kl[8][2];
            #pragma unroll
            for (int np = 0; np < 4; np++) {
                uint32_t t0, t1, t2, t3;
                ldsm4(stb + 0 * A_TILE * 2 + b_off + np * (16 * APAD * 2) + kk * 32, t0, t1, t2, t3);
                kh[2 * np][0] = t0; kh[2 * np][1] = t2;
                kh[2 * np + 1][0] = t1; kh[2 * np + 1][1] = t3;
                ldsm4(stb + 1 * A_TILE * 2 + b_off + np * (16 * APAD * 2) + kk * 32, t0, t1, t2, t3);
                kl[2 * np][0] = t0; kl[2 * np][1] = t2;
                kl[2 * np + 1][0] = t1; kl[2 * np + 1][1] = t3;
            }
            #pragma unroll
            for (int ni = 0; ni < 8; ni++)
                mma16816(s[ni], qh[kk][0], qh[kk][1], qh[kk][2], qh[kk][3],
                         kh[ni][0], kh[ni][1]);
            #pragma unroll
            for (int ni = 0; ni < 8; ni++)
                mma16816(s[ni], qh[kk][0], qh[kk][1], qh[kk][2], qh[kk][3],
                         kl[ni][0], kl[ni][1]);
            #pragma unroll
            for (int ni = 0; ni < 8; ni++)
                mma16816(s[ni], ql[kk][0], ql[kk][1], ql[kk][2], ql[kk][3],
                         kh[ni][0], kh[ni][1]);
        }

        // ---- scale into exp2 domain + causal mask (diagonal tile only) ----
        #pragma unroll
        for (int ni = 0; ni < 8; ni++)
            #pragma unroll
            for (int r = 0; r < 4; r++) s[ni][r] *= SCL2;
        if (j == iq) {
            const int rlo = w * 16 + (lane >> 2), rhi = rlo + 8;
            #pragma unroll
            for (int ni = 0; ni < 8; ni++) {
                const int c0 = ni * 8 + (lane & 3) * 2;
                if (c0 > rlo)     s[ni][0] = -1e30f;
                if (c0 + 1 > rlo) s[ni][1] = -1e30f;
                if (c0 > rhi)     s[ni][2] = -1e30f;
                if (c0 + 1 > rhi) s[ni][3] = -1e30f;
            }
        }

        // ---- online softmax (fp32, base-2) ----
        float mx_lo = s[0][0], mx_hi = s[0][2];
        #pragma unroll
        for (int ni = 0; ni < 8; ni++) {
            mx_lo = fmaxf(mx_lo, fmaxf(s[ni][0], s[ni][1]));
            mx_hi = fmaxf(mx_hi, fmaxf(s[ni][2], s[ni][3]));
        }
        mx_lo = fmaxf(mx_lo, __shfl_xor_sync(0xffffffffu, mx_lo, 1));
        mx_lo = fmaxf(mx_lo, __shfl_xor_sync(0xffffffffu, mx_lo, 2));
        mx_hi = fmaxf(mx_hi, __shfl_xor_sync(0xffffffffu, mx_hi, 1));
        mx_hi = fmaxf(mx_hi, __shfl_xor_sync(0xffffffffu, mx_hi, 2));
        const float mn_lo = fmaxf(m_lo, mx_lo), mn_hi = fmaxf(m_hi, mx_hi);
        const float al_lo = ex2f(m_lo - mn_lo), al_hi = ex2f(m_hi - mn_hi);

        uint32_t ph[8][2], pl[8][2];
        float sum_lo = 0.f, sum_hi = 0.f;
        #pragma unroll
        for (int ni = 0; ni < 8; ni++) {
            float p0 = ex2f(s[ni][0] - mn_lo);
            float p1 = ex2f(s[ni][1] - mn_lo);
            float p2 = ex2f(s[ni][2] - mn_hi);
            float p3 = ex2f(s[ni][3] - mn_hi);
            sum_lo += p0 + p1; sum_hi += p2 + p3;
            uint32_t h01 = packbf(p0, p1), h23 = packbf(p2, p3);
            ph[ni][0] = h01; ph[ni][1] = h23;
            pl[ni][0] = packbf(p0 - bflo_f(h01), p1 - bfhi_f(h01));
            pl[ni][1] = packbf(p2 - bflo_f(h23), p3 - bfhi_f(h23));
        }
        sum_lo += __shfl_xor_sync(0xffffffffu, sum_lo, 1);
        sum_lo += __shfl_xor_sync(0xffffffffu, sum_lo, 2);
        sum_hi += __shfl_xor_sync(0xffffffffu, sum_hi, 1);
        sum_hi += __shfl_xor_sync(0xffffffffu, sum_hi, 2);
        l_lo = l_lo * al_lo + sum_lo;  m_lo = mn_lo;
        l_hi = l_hi * al_hi + sum_hi;  m_hi = mn_hi;
        #pragma unroll
        for (int ni = 0; ni < 8; ni++) {
            o[ni][0] *= al_lo; o[ni][1] *= al_lo;
            o[ni][2] *= al_hi; o[ni][3] *= al_hi;
        }

        // ---- O += P V (3-term) ----
        #pragma unroll
        for (int kk = 0; kk < 4; kk++) {
            uint32_t vh[8][2], vl[8][2];
            #pragma unroll
            for (int np = 0; np < 4; np++) {
                uint32_t t0, t1, t2, t3;
                ldsm4(stb + 2 * A_TILE * 2 + b_off + np * (16 * APAD * 2) + kk * 32, t0, t1, t2, t3);
                vh[2 * np][0] = t0; vh[2 * np][1] = t2;
                vh[2 * np + 1][0] = t1; vh[2 * np + 1][1] = t3;
                ldsm4(stb + 3 * A_TILE * 2 + b_off + np * (16 * APAD * 2) + kk * 32, t0, t1, t2, t3);
                vl[2 * np][0] = t0; vl[2 * np][1] = t2;
                vl[2 * np + 1][0] = t1; vl[2 * np + 1][1] = t3;
            }
            const uint32_t pa0 = ph[2 * kk][0], pa1 = ph[2 * kk][1];
            const uint32_t pa2 = ph[2 * kk + 1][0], pa3 = ph[2 * kk + 1][1];
            const uint32_t qa0 = pl[2 * kk][0], qa1 = pl[2 * kk][1];
            const uint32_t qa2 = pl[2 * kk + 1][0], qa3 = pl[2 * kk + 1][1];
            #pragma unroll
            for (int ni = 0; ni < 8; ni++)
                mma16816(o[ni], pa0, pa1, pa2, pa3, vh[ni][0], vh[ni][1]);
            #pragma unroll
            for (int ni = 0; ni < 8; ni++)
                mma16816(o[ni], pa0, pa1, pa2, pa3, vl[ni][0], vl[ni][1]);
            #pragma unroll
            for (int ni = 0; ni < 8; ni++)
                mma16816(o[ni], qa0, qa1, qa2, qa3, vh[ni][0], vh[ni][1]);
        }
    }

    // ---- epilogue: X[b, s, h*64+dk] as bf16 hi/lo ----
    const float inv_lo = 1.f / l_lo, inv_hi = 1.f / l_hi;
    const int b = bh >> 4, h = bh & 15;
    const int s_lo = iq * 64 + w * 16 + (lane >> 2);
    const int s_hi = s_lo + 8;
    #pragma unroll
    for (int ni = 0; ni < 8; ni++) {
        const int dk = ni * 8 + (lane & 3) * 2;
        const size_t o_lo = ((size_t)(b * Ss + s_lo)) * Dd + h * DKk + dk;
        const size_t o_hi = ((size_t)(b * Ss + s_hi)) * Dd + h * DKk + dk;
        float v0 = o[ni][0] * inv_lo, v1 = o[ni][1] * inv_lo;
        float v2 = o[ni][2] * inv_hi, v3 = o[ni][3] * inv_hi;
        uint32_t hp0 = packbf(v0, v1), hp1 = packbf(v2, v3);
        *(uint32_t*)&Xhi[o_lo] = hp0;
        *(uint32_t*)&Xhi[o_hi] = hp1;
        *(uint32_t*)&Xlo[o_lo] = packbf(v0 - bflo_f(hp0), v1 - bfhi_f(hp0));
        *(uint32_t*)&Xlo[o_hi] = packbf(v2 - bflo_f(hp1), v3 - bfhi_f(hp1));
    }
    #undef ISSUE_KV
}

// ---------------------------------------------------------------------------
extern "C" void kernel_launch(void* const* d_in, const int* in_sizes, int n_in,
                              void* d_out, int out_size)
{
    const float* q   = (const float*)d_in[0];
    const float* k   = (const float*)d_in[1];
    const float* v   = (const float*)d_in[2];
    // d_in[3] = causal mask (int32) — causality computed analytically
    const float* w_q = (const float*)d_in[4];
    const float* b_q = (const float*)d_in[5];
    const float* w_k = (const float*)d_in[6];
    const float* b_k = (const float*)d_in[7];
    const float* w_v = (const float*)d_in[8];
    const float* b_v = (const float*)d_in[9];
    const float* w_o = (const float*)d_in[10];
    const float* b_o = (const float*)d_in[11];
    float* out = (float*)d_out;

    __nv_bfloat16 *pQh, *pQl, *pKh, *pKl, *pVh, *pVl, *pXh, *pXl;
    cudaGetSymbolAddress((void**)&pQh, g_Qhi);
    cudaGetSymbolAddress((void**)&pQl, g_Qlo);
    cudaGetSymbolAddress((void**)&pKh, g_Khi);
    cudaGetSymbolAddress((void**)&pKl, g_Klo);
    cudaGetSymbolAddress((void**)&pVh, g_Vthi);
    cudaGetSymbolAddress((void**)&pVl, g_Vtlo);
    cudaGetSymbolAddress((void**)&pXh, g_Xhi);
    cudaGetSymbolAddress((void**)&pXl, g_Xlo);

    cudaFuncSetAttribute(hgemm_qkv,
                         cudaFuncAttributeMaxDynamicSharedMemorySize, GSMEM);
    cudaFuncSetAttribute(hgemm_out,
                         cudaFuncAttributeMaxDynamicSharedMemorySize, GSMEM);
    cudaFuncSetAttribute(attn_mma_kernel,
                         cudaFuncAttributeMaxDynamicSharedMemorySize, ATTN_SMEM);

    // conversions (weights + activations)
    dim3 wt_grid(32, 32, 4), wt_block(32, 8);
    conv_wt_all<<<wt_grid, wt_block>>>(w_q, w_k, w_v, w_o);
    dim3 ca_grid(4096, 3);
    conv_act_all<<<ca_grid, 256>>>(q, k, v);

    // batched QKV projections
    dim3 gemm_grid(Dd / 128, Mm / 128, 3);             // (8, 32, 3)
    hgemm_qkv<<<gemm_grid, 256, GSMEM>>>(b_q, b_k, b_v);

    // attention
    dim3 agrid(Ss / 64, Bb * Hh);                      // (32, 32)
    attn_mma_kernel<<<agrid, 128, ATTN_SMEM>>>(pQh, pQl, pKh, pKl, pVh, pVl, pXh, pXl);

    // output projection
    dim3 gemm_grid1(Dd / 128, Mm / 128, 1);
    hgemm_out<<<gemm_grid1, 256, GSMEM>>>(b_o, out);
}